// round 2
// baseline (speedup 1.0000x reference)
#include <cuda_runtime.h>
#include <math.h>

#define NN 50000
#define EE 800000
#define ASTR 132   // padded smem row stride (floats), keeps 16B alignment

// ---- static device scratch (no allocs allowed) ----
__device__ float4 g_Psrc4[NN * 32];   // N x 128
__device__ float4 g_Pdst4[NN * 32];   // N x 128
__device__ float4 g_msg4 [NN * 32];   // N x 128 (atomic accum)
__device__ float  g_coord[NN * 3];
__device__ float  g_deg  [NN];

__device__ __forceinline__ float silu_f(float v) {
    return v / (1.f + __expf(-v));
}

__device__ __forceinline__ void red_add_v4(float* p, float a, float b, float c, float d) {
    asm volatile("red.global.add.v4.f32 [%0], {%1,%2,%3,%4};"
                 :: "l"(p), "f"(a), "f"(b), "f"(c), "f"(d) : "memory");
}
__device__ __forceinline__ void red_add_f(float* p, float a) {
    asm volatile("red.global.add.f32 [%0], %1;" :: "l"(p), "f"(a) : "memory");
}

// ---- zero the accumulators ----
__global__ void kZero() {
    float* msg = (float*)g_msg4;
    long total = (long)NN * 128 + NN * 3 + NN;
    for (long i = blockIdx.x * (long)blockDim.x + threadIdx.x; i < total;
         i += (long)gridDim.x * blockDim.x) {
        if (i < (long)NN * 128)            msg[i] = 0.f;
        else if (i < (long)NN * 128 + NN*3) g_coord[i - (long)NN * 128] = 0.f;
        else                                g_deg[i - (long)NN * 128 - NN * 3] = 0.f;
    }
}

// ---- shared GEMM micro-kernel: C[128x128] tile, 8x8 per thread ----
// As: [K][ASTR] transposed (cols = tile rows), Ws: [K][128]
__device__ __forceinline__ void gemm_step(const float* __restrict__ As,
                                          const float* __restrict__ Ws,
                                          int K, int tx, int ty, float acc[8][8]) {
#pragma unroll 4
    for (int k = 0; k < K; k++) {
        const float4 a0 = *(const float4*)(As + k * ASTR + ty * 8);
        const float4 a1 = *(const float4*)(As + k * ASTR + ty * 8 + 4);
        const float4 b0 = *(const float4*)(Ws + k * 128 + tx * 8);
        const float4 b1 = *(const float4*)(Ws + k * 128 + tx * 8 + 4);
        float a[8] = {a0.x, a0.y, a0.z, a0.w, a1.x, a1.y, a1.z, a1.w};
        float b[8] = {b0.x, b0.y, b0.z, b0.w, b1.x, b1.y, b1.z, b1.w};
#pragma unroll
        for (int i = 0; i < 8; i++)
#pragma unroll
            for (int j = 0; j < 8; j++)
                acc[i][j] = fmaf(a[i], b[j], acc[i][j]);
    }
}

// =====================================================================
// Kernel A: per-node precompute
//   Psrc = h @ We1[0:128] + t_emb @ We1[265:329] + be1
//   Pdst = h @ We1[128:256]
// =====================================================================
__global__ __launch_bounds__(256, 1) void kA(const float* __restrict__ h,
                                             const float* __restrict__ t_emb,
                                             const float* __restrict__ We1,
                                             const float* __restrict__ be1) {
    extern __shared__ float sm[];
    float* As = sm;                 // 128*ASTR
    float* Ts = As + 128 * ASTR;    // 64*ASTR
    float* Ws = Ts + 64 * ASTR;     // 128*128
    int tid = threadIdx.x;
    int tx = tid & 15, ty = tid >> 4;
    int tile0 = blockIdx.x * 128;

    {   // load h tile transposed: As[k][n]
        int n = tid & 127;
        int gn = tile0 + n;
        int kh = (tid >> 7) * 64;
#pragma unroll
        for (int q = 0; q < 16; q++) {
            int k = kh + q * 4;
            float4 v = make_float4(0.f, 0.f, 0.f, 0.f);
            if (gn < NN) v = *(const float4*)(h + (size_t)gn * 128 + k);
            As[(k + 0) * ASTR + n] = v.x; As[(k + 1) * ASTR + n] = v.y;
            As[(k + 2) * ASTR + n] = v.z; As[(k + 3) * ASTR + n] = v.w;
        }
        int kt = (tid >> 7) * 32;
#pragma unroll
        for (int q = 0; q < 8; q++) {
            int k = kt + q * 4;
            float4 v = make_float4(0.f, 0.f, 0.f, 0.f);
            if (gn < NN) v = *(const float4*)(t_emb + (size_t)gn * 64 + k);
            Ts[(k + 0) * ASTR + n] = v.x; Ts[(k + 1) * ASTR + n] = v.y;
            Ts[(k + 2) * ASTR + n] = v.z; Ts[(k + 3) * ASTR + n] = v.w;
        }
    }
#pragma unroll
    for (int i = 0; i < 16; i++) {   // We1 rows 0..127
        int fi = i * 256 + tid;
        ((float4*)Ws)[fi] = ((const float4*)We1)[fi];
    }
    __syncthreads();

    float acc[8][8];
#pragma unroll
    for (int i = 0; i < 8; i++)
#pragma unroll
        for (int j = 0; j < 8; j++) acc[i][j] = 0.f;
    gemm_step(As, Ws, 128, tx, ty, acc);
    __syncthreads();

#pragma unroll
    for (int i = 0; i < 8; i++) {    // We1 rows 265..328 (t_emb block)
        int fi = i * 256 + tid;
        ((float4*)Ws)[fi] = ((const float4*)(We1 + 265 * 128))[fi];
    }
    __syncthreads();
    gemm_step(Ts, Ws, 64, tx, ty, acc);

    {   // store Psrc (+be1)
        float4 b0 = *(const float4*)(be1 + tx * 8);
        float4 b1 = *(const float4*)(be1 + tx * 8 + 4);
        float bb[8] = {b0.x, b0.y, b0.z, b0.w, b1.x, b1.y, b1.z, b1.w};
        float* Psrc = (float*)g_Psrc4;
#pragma unroll
        for (int i = 0; i < 8; i++) {
            int gn = tile0 + ty * 8 + i;
            if (gn < NN) {
                *(float4*)(Psrc + (size_t)gn * 128 + tx * 8) =
                    make_float4(acc[i][0] + bb[0], acc[i][1] + bb[1],
                                acc[i][2] + bb[2], acc[i][3] + bb[3]);
                *(float4*)(Psrc + (size_t)gn * 128 + tx * 8 + 4) =
                    make_float4(acc[i][4] + bb[4], acc[i][5] + bb[5],
                                acc[i][6] + bb[6], acc[i][7] + bb[7]);
            }
        }
    }
    __syncthreads();

#pragma unroll
    for (int i = 0; i < 16; i++) {   // We1 rows 128..255
        int fi = i * 256 + tid;
        ((float4*)Ws)[fi] = ((const float4*)(We1 + 128 * 128))[fi];
    }
    __syncthreads();
#pragma unroll
    for (int i = 0; i < 8; i++)
#pragma unroll
        for (int j = 0; j < 8; j++) acc[i][j] = 0.f;
    gemm_step(As, Ws, 128, tx, ty, acc);
    {
        float* Pdst = (float*)g_Pdst4;
#pragma unroll
        for (int i = 0; i < 8; i++) {
            int gn = tile0 + ty * 8 + i;
            if (gn < NN) {
                *(float4*)(Pdst + (size_t)gn * 128 + tx * 8) =
                    make_float4(acc[i][0], acc[i][1], acc[i][2], acc[i][3]);
                *(float4*)(Pdst + (size_t)gn * 128 + tx * 8 + 4) =
                    make_float4(acc[i][4], acc[i][5], acc[i][6], acc[i][7]);
            }
        }
    }
}

// =====================================================================
// Kernel B: fused edge pipeline, 128 edges per block
// =====================================================================
__global__ __launch_bounds__(256, 1) void kB(const float* __restrict__ x,
                                             const float* __restrict__ ea,
                                             const int* __restrict__ eidx,
                                             const float* __restrict__ We1,
                                             const float* __restrict__ We2,
                                             const float* __restrict__ be2,
                                             const float* __restrict__ Watt,
                                             const float* __restrict__ batt,
                                             const float* __restrict__ Wx1,
                                             const float* __restrict__ bx1,
                                             const float* __restrict__ Wx2,
                                             const float* __restrict__ bx2) {
    extern __shared__ float sm[];
    float* Hs    = sm;                   // 128*ASTR : hidden (as [j][e]) then m (as [e][k])
    float* Ws    = Hs + 128 * ASTR;      // 128*128
    float* we1e  = Ws + 128 * 128;       // 8*128
    float* red_s = we1e + 8 * 128;       // 128*16
    float* wd_s  = red_s + 128 * 16;     // 128
    float* watt_s = wd_s + 128;
    float* be2_s  = watt_s + 128;
    float* bx1_s  = be2_s + 128;
    float* wx2_s  = bx1_s + 128;
    float* att_s  = wx2_s + 128;
    float* dsq_s  = att_s + 128;
    float* diff_s = dsq_s + 128;         // 128*3
    int* src_s = (int*)(diff_s + 128 * 3);
    int* dst_s = src_s + 128;

    int tid = threadIdx.x;
    int tx = tid & 15, ty = tid >> 4;
    int e0 = blockIdx.x * 128;

    if (tid < 128) {
        int e = e0 + tid;
        int s = eidx[e], d = eidx[EE + e];
        src_s[tid] = s; dst_s[tid] = d;
        float dx = x[s * 3 + 0] - x[d * 3 + 0];
        float dy = x[s * 3 + 1] - x[d * 3 + 1];
        float dz = x[s * 3 + 2] - x[d * 3 + 2];
        diff_s[tid * 3 + 0] = dx; diff_s[tid * 3 + 1] = dy; diff_s[tid * 3 + 2] = dz;
        dsq_s[tid] = dx * dx + dy * dy + dz * dz;
        wd_s[tid]   = We1[256 * 128 + tid];
        watt_s[tid] = Watt[tid];
        be2_s[tid]  = be2[tid];
        bx1_s[tid]  = bx1[tid];
        wx2_s[tid]  = Wx2[tid];
    }
    {   // We1 rows 257..264 (edge_attr block), 1024 floats
        ((float4*)we1e)[tid] = ((const float4*)(We1 + 257 * 128))[tid];
    }
#pragma unroll
    for (int i = 0; i < 16; i++) {       // stage We2
        int fi = i * 256 + tid;
        ((float4*)Ws)[fi] = ((const float4*)We2)[fi];
    }
    __syncthreads();

    {   // hidden = silu(Psrc[src]+Pdst[dst]+dsq*wd+ea@We1e), store transposed Hs[j][e]
        int e = tid >> 1;
        int j0 = (tid & 1) * 64;
        int s = src_s[e], d = dst_s[e];
        float dsq = dsq_s[e];
        float4 e0v = *(const float4*)(ea + (size_t)(e0 + e) * 8);
        float4 e1v = *(const float4*)(ea + (size_t)(e0 + e) * 8 + 4);
        float ear[8] = {e0v.x, e0v.y, e0v.z, e0v.w, e1v.x, e1v.y, e1v.z, e1v.w};
        const float4* ps = (const float4*)((float*)g_Psrc4 + (size_t)s * 128 + j0);
        const float4* pd = (const float4*)((float*)g_Pdst4 + (size_t)d * 128 + j0);
#pragma unroll
        for (int q = 0; q < 16; q++) {
            float4 a = ps[q], b = pd[q];
            int j = j0 + q * 4;
            float4 w = *(const float4*)(wd_s + j);
            float p0 = fmaf(dsq, w.x, a.x + b.x);
            float p1 = fmaf(dsq, w.y, a.y + b.y);
            float p2 = fmaf(dsq, w.z, a.z + b.z);
            float p3 = fmaf(dsq, w.w, a.w + b.w);
#pragma unroll
            for (int t = 0; t < 8; t++) {
                float4 wv = *(const float4*)(we1e + t * 128 + j);
                p0 = fmaf(ear[t], wv.x, p0);
                p1 = fmaf(ear[t], wv.y, p1);
                p2 = fmaf(ear[t], wv.z, p2);
                p3 = fmaf(ear[t], wv.w, p3);
            }
            Hs[(j + 0) * ASTR + e] = silu_f(p0);
            Hs[(j + 1) * ASTR + e] = silu_f(p1);
            Hs[(j + 2) * ASTR + e] = silu_f(p2);
            Hs[(j + 3) * ASTR + e] = silu_f(p3);
        }
    }
    __syncthreads();

    // GEMM1: m = hidden @ We2 + be2
    float acc[8][8];
#pragma unroll
    for (int i = 0; i < 8; i++)
#pragma unroll
        for (int j = 0; j < 8; j++) acc[i][j] = 0.f;
    gemm_step(Hs, Ws, 128, tx, ty, acc);
    {
        float bb[8], wa[8];
#pragma unroll
        for (int j = 0; j < 8; j++) { bb[j] = be2_s[tx * 8 + j]; wa[j] = watt_s[tx * 8 + j]; }
#pragma unroll
        for (int i = 0; i < 8; i++) {
            float p = 0.f;
#pragma unroll
            for (int j = 0; j < 8; j++) {
                acc[i][j] += bb[j];
                p = fmaf(acc[i][j], wa[j], p);
            }
            red_s[(ty * 8 + i) * 16 + tx] = p;
        }
    }
    __syncthreads();
    if (tid < 128) {   // att = sigmoid(m @ Watt + batt)
        float s = batt[0];
#pragma unroll
        for (int t = 0; t < 16; t++) s += red_s[tid * 16 + t];
        att_s[tid] = 1.f / (1.f + __expf(-s));
    }
    __syncthreads();
#pragma unroll
    for (int i = 0; i < 8; i++) {
        float at = att_s[ty * 8 + i];
#pragma unroll
        for (int j = 0; j < 8; j++) acc[i][j] *= at;
    }
    // scatter msg_agg
    {
        float* msg = (float*)g_msg4;
#pragma unroll
        for (int i = 0; i < 8; i++) {
            int d = dst_s[ty * 8 + i];
            float* p = msg + (size_t)d * 128 + tx * 8;
            red_add_v4(p,     acc[i][0], acc[i][1], acc[i][2], acc[i][3]);
            red_add_v4(p + 4, acc[i][4], acc[i][5], acc[i][6], acc[i][7]);
        }
    }
    __syncthreads();   // all GEMM1 reads of Hs/Ws complete

    // store m row-major: Hs reused as Ms[e][k]
#pragma unroll
    for (int i = 0; i < 8; i++) {
        *(float4*)(Hs + (size_t)(ty * 8 + i) * ASTR + tx * 8) =
            make_float4(acc[i][0], acc[i][1], acc[i][2], acc[i][3]);
        *(float4*)(Hs + (size_t)(ty * 8 + i) * ASTR + tx * 8 + 4) =
            make_float4(acc[i][4], acc[i][5], acc[i][6], acc[i][7]);
    }
#pragma unroll
    for (int i = 0; i < 16; i++) {       // stage Wx1
        int fi = i * 256 + tid;
        ((float4*)Ws)[fi] = ((const float4*)Wx1)[fi];
    }
    __syncthreads();

    // GEMM2: g = silu(m @ Wx1 + bx1);   coordw_partial = g @ Wx2
    float acc2[8][8];
#pragma unroll
    for (int i = 0; i < 8; i++)
#pragma unroll
        for (int j = 0; j < 8; j++) acc2[i][j] = 0.f;
#pragma unroll 2
    for (int k = 0; k < 128; k++) {
        float a[8];
#pragma unroll
        for (int i = 0; i < 8; i++) a[i] = Hs[(ty * 8 + i) * ASTR + k];
        float4 b0 = *(const float4*)(Ws + k * 128 + tx * 8);
        float4 b1 = *(const float4*)(Ws + k * 128 + tx * 8 + 4);
        float b[8] = {b0.x, b0.y, b0.z, b0.w, b1.x, b1.y, b1.z, b1.w};
#pragma unroll
        for (int i = 0; i < 8; i++)
#pragma unroll
            for (int j = 0; j < 8; j++)
                acc2[i][j] = fmaf(a[i], b[j], acc2[i][j]);
    }
    {
        float bb[8], w2[8];
#pragma unroll
        for (int j = 0; j < 8; j++) { bb[j] = bx1_s[tx * 8 + j]; w2[j] = wx2_s[tx * 8 + j]; }
#pragma unroll
        for (int i = 0; i < 8; i++) {
            float p = 0.f;
#pragma unroll
            for (int j = 0; j < 8; j++) {
                float g = silu_f(acc2[i][j] + bb[j]);
                p = fmaf(g, w2[j], p);
            }
            red_s[(ty * 8 + i) * 16 + tx] = p;
        }
    }
    __syncthreads();
    if (tid < 128) {   // coord_w = tanh(...), scatter coord + deg
        float s = bx2[0];
#pragma unroll
        for (int t = 0; t < 16; t++) s += red_s[tid * 16 + t];
        float cw = tanhf(s);
        int d = dst_s[tid];
        red_add_f(g_coord + (size_t)d * 3 + 0, diff_s[tid * 3 + 0] * cw);
        red_add_f(g_coord + (size_t)d * 3 + 1, diff_s[tid * 3 + 1] * cw);
        red_add_f(g_coord + (size_t)d * 3 + 2, diff_s[tid * 3 + 2] * cw);
        red_add_f(g_deg + d, 1.0f);
    }
}

// =====================================================================
// Kernel C: node update  h_out = h + silu([h|msg]@Wh1+b)@Wh2+b
// =====================================================================
__global__ __launch_bounds__(256, 1) void kC(const float* __restrict__ h,
                                             const float* __restrict__ Wh1,
                                             const float* __restrict__ bh1,
                                             const float* __restrict__ Wh2,
                                             const float* __restrict__ bh2,
                                             float* __restrict__ out) {
    extern __shared__ float sm[];
    float* Gs = sm;               // 128*ASTR (first 64*ASTR doubles as A-chunk)
    float* Wc = Gs + 128 * ASTR;  // 64*128
    int tid = threadIdx.x;
    int tx = tid & 15, ty = tid >> 4;
    int tile0 = blockIdx.x * 128;

    float acc[8][8];
#pragma unroll
    for (int i = 0; i < 8; i++)
#pragma unroll
        for (int j = 0; j < 8; j++) acc[i][j] = 0.f;

    for (int c = 0; c < 4; c++) {
        const float* srcmat = (c < 2) ? h : (const float*)g_msg4;
        int kbase = (c & 1) * 64;
        {   // load A chunk transposed
            int n = tid & 127;
            int gn = tile0 + n;
            int ks = (tid >> 7) * 32;
#pragma unroll
            for (int q = 0; q < 8; q++) {
                int k = ks + q * 4;
                float4 v = make_float4(0.f, 0.f, 0.f, 0.f);
                if (gn < NN) v = *(const float4*)(srcmat + (size_t)gn * 128 + kbase + k);
                Gs[(k + 0) * ASTR + n] = v.x; Gs[(k + 1) * ASTR + n] = v.y;
                Gs[(k + 2) * ASTR + n] = v.z; Gs[(k + 3) * ASTR + n] = v.w;
            }
        }
#pragma unroll
        for (int i = 0; i < 8; i++) {
            int fi = i * 256 + tid;
            ((float4*)Wc)[fi] = ((const float4*)(Wh1 + (size_t)c * 64 * 128))[fi];
        }
        __syncthreads();
        gemm_step(Gs, Wc, 64, tx, ty, acc);
        __syncthreads();
    }
    {   // g = silu(acc + bh1), store row-major Gs[n][k]
        float4 b0 = *(const float4*)(bh1 + tx * 8);
        float4 b1 = *(const float4*)(bh1 + tx * 8 + 4);
        float bb[8] = {b0.x, b0.y, b0.z, b0.w, b1.x, b1.y, b1.z, b1.w};
#pragma unroll
        for (int i = 0; i < 8; i++) {
            *(float4*)(Gs + (size_t)(ty * 8 + i) * ASTR + tx * 8) =
                make_float4(silu_f(acc[i][0] + bb[0]), silu_f(acc[i][1] + bb[1]),
                            silu_f(acc[i][2] + bb[2]), silu_f(acc[i][3] + bb[3]));
            *(float4*)(Gs + (size_t)(ty * 8 + i) * ASTR + tx * 8 + 4) =
                make_float4(silu_f(acc[i][4] + bb[4]), silu_f(acc[i][5] + bb[5]),
                            silu_f(acc[i][6] + bb[6]), silu_f(acc[i][7] + bb[7]));
        }
    }
    __syncthreads();

    float acc2[8][8];
#pragma unroll
    for (int i = 0; i < 8; i++)
#pragma unroll
        for (int j = 0; j < 8; j++) acc2[i][j] = 0.f;
    for (int c = 0; c < 2; c++) {
#pragma unroll
        for (int i = 0; i < 8; i++) {
            int fi = i * 256 + tid;
            ((float4*)Wc)[fi] = ((const float4*)(Wh2 + (size_t)c * 64 * 128))[fi];
        }
        __syncthreads();
#pragma unroll 2
        for (int k = 0; k < 64; k++) {
            float a[8];
#pragma unroll
            for (int i = 0; i < 8; i++) a[i] = Gs[(ty * 8 + i) * ASTR + c * 64 + k];
            float4 b0 = *(const float4*)(Wc + k * 128 + tx * 8);
            float4 b1 = *(const float4*)(Wc + k * 128 + tx * 8 + 4);
            float b[8] = {b0.x, b0.y, b0.z, b0.w, b1.x, b1.y, b1.z, b1.w};
#pragma unroll
            for (int i = 0; i < 8; i++)
#pragma unroll
                for (int j = 0; j < 8; j++)
                    acc2[i][j] = fmaf(a[i], b[j], acc2[i][j]);
        }
        __syncthreads();
    }
    {   // h_out = h + acc2 + bh2
        float4 b0 = *(const float4*)(bh2 + tx * 8);
        float4 b1 = *(const float4*)(bh2 + tx * 8 + 4);
        float bb[8] = {b0.x, b0.y, b0.z, b0.w, b1.x, b1.y, b1.z, b1.w};
#pragma unroll
        for (int i = 0; i < 8; i++) {
            int gn = tile0 + ty * 8 + i;
            if (gn < NN) {
                float4 h0 = *(const float4*)(h + (size_t)gn * 128 + tx * 8);
                float4 h1 = *(const float4*)(h + (size_t)gn * 128 + tx * 8 + 4);
                *(float4*)(out + (size_t)gn * 128 + tx * 8) =
                    make_float4(h0.x + acc2[i][0] + bb[0], h0.y + acc2[i][1] + bb[1],
                                h0.z + acc2[i][2] + bb[2], h0.w + acc2[i][3] + bb[3]);
                *(float4*)(out + (size_t)gn * 128 + tx * 8 + 4) =
                    make_float4(h1.x + acc2[i][4] + bb[4], h1.y + acc2[i][5] + bb[5],
                                h1.z + acc2[i][6] + bb[6], h1.w + acc2[i][7] + bb[7]);
            }
        }
    }
}

// ---- x_out ----
__global__ void kX(const float* __restrict__ x, float* __restrict__ out) {
    int n = blockIdx.x * blockDim.x + threadIdx.x;
    if (n < NN) {
        float inv = 1.f / (g_deg[n] + 1.f);
        float* o = out + (size_t)NN * 128 + (size_t)n * 3;
        o[0] = x[n * 3 + 0] + g_coord[n * 3 + 0] * inv;
        o[1] = x[n * 3 + 1] + g_coord[n * 3 + 1] * inv;
        o[2] = x[n * 3 + 2] + g_coord[n * 3 + 2] * inv;
    }
}

extern "C" void kernel_launch(void* const* d_in, const int* in_sizes, int n_in,
                              void* d_out, int out_size) {
    const float* h    = (const float*)d_in[0];
    const float* x    = (const float*)d_in[1];
    const float* ea   = (const float*)d_in[2];
    const float* temb = (const float*)d_in[3];
    const float* We1w = (const float*)d_in[4];
    const float* We1b = (const float*)d_in[5];
    const float* We2w = (const float*)d_in[6];
    const float* We2b = (const float*)d_in[7];
    const float* Wattw = (const float*)d_in[8];
    const float* Wattb = (const float*)d_in[9];
    const float* Wx1w = (const float*)d_in[10];
    const float* Wx1b = (const float*)d_in[11];
    const float* Wx2w = (const float*)d_in[12];
    const float* Wx2b = (const float*)d_in[13];
    const float* Wh1w = (const float*)d_in[14];
    const float* Wh1b = (const float*)d_in[15];
    const float* Wh2w = (const float*)d_in[16];
    const float* Wh2b = (const float*)d_in[17];
    const int*   eidx = (const int*)d_in[18];
    float* out = (float*)d_out;

    const int smA = (128 * ASTR + 64 * ASTR + 128 * 128) * 4;
    const int smB = (128 * ASTR + 128 * 128 + 8 * 128 + 128 * 16 +
                     7 * 128 + 128 * 3 + 256) * 4;
    const int smC = (128 * ASTR + 64 * 128) * 4;
    cudaFuncSetAttribute(kA, cudaFuncAttributeMaxDynamicSharedMemorySize, smA);
    cudaFuncSetAttribute(kB, cudaFuncAttributeMaxDynamicSharedMemorySize, smB);
    cudaFuncSetAttribute(kC, cudaFuncAttributeMaxDynamicSharedMemorySize, smC);

    kZero<<<4096, 256>>>();
    kA<<<(NN + 127) / 128, 256, smA>>>(h, temb, We1w, We1b);
    kB<<<EE / 128, 256, smB>>>(x, ea, eidx, We1w, We2w, We2b,
                               Wattw, Wattb, Wx1w, Wx1b, Wx2w, Wx2b);
    kC<<<(NN + 127) / 128, 256, smC>>>(h, Wh1w, Wh1b, Wh2w, Wh2b, out);
    kX<<<(NN + 255) / 256, 256>>>(x, out);
}

// round 3
// speedup vs baseline: 1.7429x; 1.7429x over previous
#include <cuda_runtime.h>
#include <math.h>
#include <stdint.h>

#define NN 50000
#define EE 800000
#define ASTR 132   // A-tile smem stride (floats): banks 4g+t unique -> conflict-free
#define WSTR 136   // B-tile smem stride (floats): banks 8t+g unique -> conflict-free

// ---- static device scratch (no allocs allowed) ----
__device__ float4 g_Psrc4[NN * 32];   // N x 128
__device__ float4 g_Pdst4[NN * 32];   // N x 128
__device__ float4 g_msg4 [NN * 32];   // N x 128 (atomic accum)
__device__ float  g_coord[NN * 3];
__device__ float  g_deg  [NN];

__device__ __forceinline__ float silu_f(float v) {
    return v / (1.f + __expf(-v));
}
__device__ __forceinline__ void red_add_v4(float* p, float a, float b, float c, float d) {
    asm volatile("red.global.add.v4.f32 [%0], {%1,%2,%3,%4};"
                 :: "l"(p), "f"(a), "f"(b), "f"(c), "f"(d) : "memory");
}
__device__ __forceinline__ void red_add_f(float* p, float a) {
    asm volatile("red.global.add.f32 [%0], %1;" :: "l"(p), "f"(a) : "memory");
}
__device__ __forceinline__ uint32_t f2tf(float f) {
    uint32_t u;
    asm("cvt.rna.tf32.f32 %0, %1;" : "=r"(u) : "f"(f));
    return u;
}
__device__ __forceinline__ void mma_tf32(float c[4], const uint32_t a[4], const uint32_t b[2]) {
    asm volatile("mma.sync.aligned.m16n8k8.row.col.f32.tf32.tf32.f32 "
                 "{%0,%1,%2,%3}, {%4,%5,%6,%7}, {%8,%9}, {%0,%1,%2,%3};"
                 : "+f"(c[0]), "+f"(c[1]), "+f"(c[2]), "+f"(c[3])
                 : "r"(a[0]), "r"(a[1]), "r"(a[2]), "r"(a[3]),
                   "r"(b[0]), "r"(b[1]));
}

// stage 128x128 fp32 weight -> tf32 bits in smem, stride WSTR (256 threads)
__device__ __forceinline__ void stage_w(const float* __restrict__ src,
                                        uint32_t* __restrict__ Ws, int tid) {
#pragma unroll
    for (int i = 0; i < 16; i++) {
        int f = i * 256 + tid;
        float4 v = ((const float4*)src)[f];
        int row = f >> 5, q = (f & 31) * 4;
        uint32_t* p = Ws + row * WSTR + q;
        p[0] = f2tf(v.x); p[1] = f2tf(v.y); p[2] = f2tf(v.z); p[3] = f2tf(v.w);
    }
}

// warp-level tf32 GEMM: C[32x64 per warp] += A[128xK] * B[KxN]
// Hs: A tile row-major stride ASTR (fp32 if CVTA, else tf32 bits)
// Ws: B tile row-major over k, stride WSTR, tf32 bits
template<bool CVTA>
__device__ __forceinline__ void mma_gemm(const uint32_t* __restrict__ Hs,
                                         const uint32_t* __restrict__ Ws,
                                         int K, int m0, int n0, int g4, int t4,
                                         float acc[2][8][4]) {
#pragma unroll 2
    for (int k0 = 0; k0 < K; k0 += 8) {
        uint32_t b[8][2];
#pragma unroll
        for (int j = 0; j < 8; j++) {
            b[j][0] = Ws[(k0 + t4) * WSTR + n0 + 8 * j + g4];
            b[j][1] = Ws[(k0 + t4 + 4) * WSTR + n0 + 8 * j + g4];
        }
#pragma unroll
        for (int mt = 0; mt < 2; mt++) {
            int r = m0 + 16 * mt + g4;
            uint32_t a[4];
            a[0] = Hs[r * ASTR + k0 + t4];
            a[1] = Hs[(r + 8) * ASTR + k0 + t4];
            a[2] = Hs[r * ASTR + k0 + t4 + 4];
            a[3] = Hs[(r + 8) * ASTR + k0 + t4 + 4];
            if (CVTA) {
                a[0] = f2tf(__uint_as_float(a[0]));
                a[1] = f2tf(__uint_as_float(a[1]));
                a[2] = f2tf(__uint_as_float(a[2]));
                a[3] = f2tf(__uint_as_float(a[3]));
            }
#pragma unroll
            for (int j = 0; j < 8; j++) mma_tf32(acc[mt][j], a, b[j]);
        }
    }
}

// ---- zero the accumulators ----
__global__ void kZero() {
    float* msg = (float*)g_msg4;
    long total = (long)NN * 128 + NN * 3 + NN;
    for (long i = blockIdx.x * (long)blockDim.x + threadIdx.x; i < total;
         i += (long)gridDim.x * blockDim.x) {
        if (i < (long)NN * 128)            msg[i] = 0.f;
        else if (i < (long)NN * 128 + NN*3) g_coord[i - (long)NN * 128] = 0.f;
        else                                g_deg[i - (long)NN * 128 - NN * 3] = 0.f;
    }
}

// ---- fp32 GEMM micro-kernel (kA only) ----
__device__ __forceinline__ void gemm_step(const float* __restrict__ As,
                                          const float* __restrict__ Ws,
                                          int K, int tx, int ty, float acc[8][8]) {
#pragma unroll 4
    for (int k = 0; k < K; k++) {
        const float4 a0 = *(const float4*)(As + k * ASTR + ty * 8);
        const float4 a1 = *(const float4*)(As + k * ASTR + ty * 8 + 4);
        const float4 b0 = *(const float4*)(Ws + k * 128 + tx * 8);
        const float4 b1 = *(const float4*)(Ws + k * 128 + tx * 8 + 4);
        float a[8] = {a0.x, a0.y, a0.z, a0.w, a1.x, a1.y, a1.z, a1.w};
        float b[8] = {b0.x, b0.y, b0.z, b0.w, b1.x, b1.y, b1.z, b1.w};
#pragma unroll
        for (int i = 0; i < 8; i++)
#pragma unroll
            for (int j = 0; j < 8; j++)
                acc[i][j] = fmaf(a[i], b[j], acc[i][j]);
    }
}

// =====================================================================
// Kernel A: per-node precompute (fp32, unchanged)
// =====================================================================
__global__ __launch_bounds__(256, 1) void kA(const float* __restrict__ h,
                                             const float* __restrict__ t_emb,
                                             const float* __restrict__ We1,
                                             const float* __restrict__ be1) {
    extern __shared__ float sm[];
    float* As = sm;                 // 128*ASTR
    float* Ts = As + 128 * ASTR;    // 64*ASTR
    float* Ws = Ts + 64 * ASTR;     // 128*128
    int tid = threadIdx.x;
    int tx = tid & 15, ty = tid >> 4;
    int tile0 = blockIdx.x * 128;

    {
        int n = tid & 127;
        int gn = tile0 + n;
        int kh = (tid >> 7) * 64;
#pragma unroll
        for (int q = 0; q < 16; q++) {
            int k = kh + q * 4;
            float4 v = make_float4(0.f, 0.f, 0.f, 0.f);
            if (gn < NN) v = *(const float4*)(h + (size_t)gn * 128 + k);
            As[(k + 0) * ASTR + n] = v.x; As[(k + 1) * ASTR + n] = v.y;
            As[(k + 2) * ASTR + n] = v.z; As[(k + 3) * ASTR + n] = v.w;
        }
        int kt = (tid >> 7) * 32;
#pragma unroll
        for (int q = 0; q < 8; q++) {
            int k = kt + q * 4;
            float4 v = make_float4(0.f, 0.f, 0.f, 0.f);
            if (gn < NN) v = *(const float4*)(t_emb + (size_t)gn * 64 + k);
            Ts[(k + 0) * ASTR + n] = v.x; Ts[(k + 1) * ASTR + n] = v.y;
            Ts[(k + 2) * ASTR + n] = v.z; Ts[(k + 3) * ASTR + n] = v.w;
        }
    }
#pragma unroll
    for (int i = 0; i < 16; i++) {
        int fi = i * 256 + tid;
        ((float4*)Ws)[fi] = ((const float4*)We1)[fi];
    }
    __syncthreads();

    float acc[8][8];
#pragma unroll
    for (int i = 0; i < 8; i++)
#pragma unroll
        for (int j = 0; j < 8; j++) acc[i][j] = 0.f;
    gemm_step(As, Ws, 128, tx, ty, acc);
    __syncthreads();

#pragma unroll
    for (int i = 0; i < 8; i++) {
        int fi = i * 256 + tid;
        ((float4*)Ws)[fi] = ((const float4*)(We1 + 265 * 128))[fi];
    }
    __syncthreads();
    gemm_step(Ts, Ws, 64, tx, ty, acc);

    {
        float4 b0 = *(const float4*)(be1 + tx * 8);
        float4 b1 = *(const float4*)(be1 + tx * 8 + 4);
        float bb[8] = {b0.x, b0.y, b0.z, b0.w, b1.x, b1.y, b1.z, b1.w};
        float* Psrc = (float*)g_Psrc4;
#pragma unroll
        for (int i = 0; i < 8; i++) {
            int gn = tile0 + ty * 8 + i;
            if (gn < NN) {
                *(float4*)(Psrc + (size_t)gn * 128 + tx * 8) =
                    make_float4(acc[i][0] + bb[0], acc[i][1] + bb[1],
                                acc[i][2] + bb[2], acc[i][3] + bb[3]);
                *(float4*)(Psrc + (size_t)gn * 128 + tx * 8 + 4) =
                    make_float4(acc[i][4] + bb[4], acc[i][5] + bb[5],
                                acc[i][6] + bb[6], acc[i][7] + bb[7]);
            }
        }
    }
    __syncthreads();

#pragma unroll
    for (int i = 0; i < 16; i++) {
        int fi = i * 256 + tid;
        ((float4*)Ws)[fi] = ((const float4*)(We1 + 128 * 128))[fi];
    }
    __syncthreads();
#pragma unroll
    for (int i = 0; i < 8; i++)
#pragma unroll
        for (int j = 0; j < 8; j++) acc[i][j] = 0.f;
    gemm_step(As, Ws, 128, tx, ty, acc);
    {
        float* Pdst = (float*)g_Pdst4;
#pragma unroll
        for (int i = 0; i < 8; i++) {
            int gn = tile0 + ty * 8 + i;
            if (gn < NN) {
                *(float4*)(Pdst + (size_t)gn * 128 + tx * 8) =
                    make_float4(acc[i][0], acc[i][1], acc[i][2], acc[i][3]);
                *(float4*)(Pdst + (size_t)gn * 128 + tx * 8 + 4) =
                    make_float4(acc[i][4], acc[i][5], acc[i][6], acc[i][7]);
            }
        }
    }
}

// =====================================================================
// Kernel B: fused edge pipeline (tensor-core tf32), 128 edges per block
// =====================================================================
__global__ __launch_bounds__(256, 1) void kB(const float* __restrict__ x,
                                             const float* __restrict__ ea,
                                             const int* __restrict__ eidx,
                                             const float* __restrict__ We1,
                                             const float* __restrict__ We2,
                                             const float* __restrict__ be2,
                                             const float* __restrict__ Watt,
                                             const float* __restrict__ batt,
                                             const float* __restrict__ Wx1,
                                             const float* __restrict__ bx1,
                                             const float* __restrict__ Wx2,
                                             const float* __restrict__ bx2) {
    extern __shared__ float sm[];
    float*    Hs   = sm;                              // 128*ASTR fp32 (hidden, then m)
    uint32_t* Ws   = (uint32_t*)(Hs + 128 * ASTR);    // 128*WSTR tf32 bits
    float*    we1e = (float*)(Ws + 128 * WSTR);       // 8*128
    float*    red_s = we1e + 8 * 128;                 // 128*2
    float*    wd_s  = red_s + 256;                    // 128
    float*    watt_s = wd_s + 128;
    float*    be2_s  = watt_s + 128;
    float*    bx1_s  = be2_s + 128;
    float*    wx2_s  = bx1_s + 128;
    float*    att_s  = wx2_s + 128;
    float*    dsq_s  = att_s + 128;
    float*    diff_s = dsq_s + 128;                   // 128*3
    int* src_s = (int*)(diff_s + 128 * 3);
    int* dst_s = src_s + 128;

    int tid = threadIdx.x;
    int lane = tid & 31, w = tid >> 5;
    int g4 = lane >> 2, t4 = lane & 3;
    int m0 = (w & 3) * 32, n0 = (w >> 2) * 64;
    int e0 = blockIdx.x * 128;

    if (tid < 128) {
        int e = e0 + tid;
        int s = eidx[e], d = eidx[EE + e];
        src_s[tid] = s; dst_s[tid] = d;
        float dx = x[s * 3 + 0] - x[d * 3 + 0];
        float dy = x[s * 3 + 1] - x[d * 3 + 1];
        float dz = x[s * 3 + 2] - x[d * 3 + 2];
        diff_s[tid * 3 + 0] = dx; diff_s[tid * 3 + 1] = dy; diff_s[tid * 3 + 2] = dz;
        dsq_s[tid] = dx * dx + dy * dy + dz * dz;
        wd_s[tid]   = We1[256 * 128 + tid];
        watt_s[tid] = Watt[tid];
        be2_s[tid]  = be2[tid];
        bx1_s[tid]  = bx1[tid];
        wx2_s[tid]  = Wx2[tid];
    }
    ((float4*)we1e)[tid] = ((const float4*)(We1 + 257 * 128))[tid];
    stage_w(We2, Ws, tid);
    __syncthreads();

    {   // hidden = silu(Psrc[src]+Pdst[dst]+dsq*wd+ea@We1e), row-major Hs[e][j]
        int e = tid >> 1;
        int j0 = (tid & 1) * 64;
        int s = src_s[e], d = dst_s[e];
        float dsq = dsq_s[e];
        float4 e0v = *(const float4*)(ea + (size_t)(e0 + e) * 8);
        float4 e1v = *(const float4*)(ea + (size_t)(e0 + e) * 8 + 4);
        float ear[8] = {e0v.x, e0v.y, e0v.z, e0v.w, e1v.x, e1v.y, e1v.z, e1v.w};
        const float4* ps = (const float4*)((float*)g_Psrc4 + (size_t)s * 128 + j0);
        const float4* pd = (const float4*)((float*)g_Pdst4 + (size_t)d * 128 + j0);
#pragma unroll
        for (int q = 0; q < 16; q++) {
            float4 a = ps[q], b = pd[q];
            int j = j0 + q * 4;
            float4 wv = *(const float4*)(wd_s + j);
            float p0 = fmaf(dsq, wv.x, a.x + b.x);
            float p1 = fmaf(dsq, wv.y, a.y + b.y);
            float p2 = fmaf(dsq, wv.z, a.z + b.z);
            float p3 = fmaf(dsq, wv.w, a.w + b.w);
#pragma unroll
            for (int tt = 0; tt < 8; tt++) {
                float4 we = *(const float4*)(we1e + tt * 128 + j);
                p0 = fmaf(ear[tt], we.x, p0);
                p1 = fmaf(ear[tt], we.y, p1);
                p2 = fmaf(ear[tt], we.z, p2);
                p3 = fmaf(ear[tt], we.w, p3);
            }
            *(float4*)(Hs + (size_t)e * ASTR + j) =
                make_float4(silu_f(p0), silu_f(p1), silu_f(p2), silu_f(p3));
        }
    }
    __syncthreads();

    // GEMM1: m = hidden @ We2
    float acc[2][8][4];
#pragma unroll
    for (int mt = 0; mt < 2; mt++)
#pragma unroll
        for (int j = 0; j < 8; j++)
#pragma unroll
            for (int q = 0; q < 4; q++) acc[mt][j][q] = 0.f;
    mma_gemm<true>((const uint32_t*)Hs, Ws, 128, m0, n0, g4, t4, acc);

    // epilogue1: bias + att partial dot
    float pA[2], pB[2];
#pragma unroll
    for (int mt = 0; mt < 2; mt++) {
        pA[mt] = 0.f; pB[mt] = 0.f;
#pragma unroll
        for (int j = 0; j < 8; j++) {
            int c = n0 + 8 * j + 2 * t4;
            float b0 = be2_s[c], b1 = be2_s[c + 1];
            float w0 = watt_s[c], w1 = watt_s[c + 1];
            acc[mt][j][0] += b0; acc[mt][j][1] += b1;
            acc[mt][j][2] += b0; acc[mt][j][3] += b1;
            pA[mt] = fmaf(acc[mt][j][0], w0, fmaf(acc[mt][j][1], w1, pA[mt]));
            pB[mt] = fmaf(acc[mt][j][2], w0, fmaf(acc[mt][j][3], w1, pB[mt]));
        }
        pA[mt] += __shfl_xor_sync(0xffffffffu, pA[mt], 1);
        pA[mt] += __shfl_xor_sync(0xffffffffu, pA[mt], 2);
        pB[mt] += __shfl_xor_sync(0xffffffffu, pB[mt], 1);
        pB[mt] += __shfl_xor_sync(0xffffffffu, pB[mt], 2);
        if (t4 == 0) {
            red_s[(m0 + 16 * mt + g4) * 2 + (w >> 2)] = pA[mt];
            red_s[(m0 + 16 * mt + g4 + 8) * 2 + (w >> 2)] = pB[mt];
        }
    }
    __syncthreads();
    if (tid < 128) {
        float s = red_s[tid * 2] + red_s[tid * 2 + 1] + batt[0];
        att_s[tid] = 1.f / (1.f + __expf(-s));
    }
    __syncthreads();

    // gate + store m into Hs; stage Wx1
#pragma unroll
    for (int mt = 0; mt < 2; mt++) {
        int rA = m0 + 16 * mt + g4;
        float aA = att_s[rA], aB = att_s[rA + 8];
#pragma unroll
        for (int j = 0; j < 8; j++) {
            int c = n0 + 8 * j + 2 * t4;
            *(float2*)(Hs + (size_t)rA * ASTR + c) =
                make_float2(acc[mt][j][0] * aA, acc[mt][j][1] * aA);
            *(float2*)(Hs + (size_t)(rA + 8) * ASTR + c) =
                make_float2(acc[mt][j][2] * aB, acc[mt][j][3] * aB);
        }
    }
    stage_w(Wx1, Ws, tid);
    __syncthreads();

    // scatter msg_agg from Hs
    {
        int r = tid >> 1, j0 = (tid & 1) * 64;
        int d = dst_s[r];
        float* p = (float*)g_msg4 + (size_t)d * 128 + j0;
#pragma unroll
        for (int q = 0; q < 16; q++) {
            float4 v = *(const float4*)(Hs + (size_t)r * ASTR + j0 + q * 4);
            red_add_v4(p + q * 4, v.x, v.y, v.z, v.w);
        }
    }

    // GEMM2: g = silu(m @ Wx1 + bx1); coordw partial = g @ Wx2
    float acc2[2][8][4];
#pragma unroll
    for (int mt = 0; mt < 2; mt++)
#pragma unroll
        for (int j = 0; j < 8; j++)
#pragma unroll
            for (int q = 0; q < 4; q++) acc2[mt][j][q] = 0.f;
    mma_gemm<true>((const uint32_t*)Hs, Ws, 128, m0, n0, g4, t4, acc2);

#pragma unroll
    for (int mt = 0; mt < 2; mt++) {
        pA[mt] = 0.f; pB[mt] = 0.f;
#pragma unroll
        for (int j = 0; j < 8; j++) {
            int c = n0 + 8 * j + 2 * t4;
            float b0 = bx1_s[c], b1 = bx1_s[c + 1];
            float w0 = wx2_s[c], w1 = wx2_s[c + 1];
            float g0 = silu_f(acc2[mt][j][0] + b0);
            float g1 = silu_f(acc2[mt][j][1] + b1);
            float g2 = silu_f(acc2[mt][j][2] + b0);
            float g3 = silu_f(acc2[mt][j][3] + b1);
            pA[mt] = fmaf(g0, w0, fmaf(g1, w1, pA[mt]));
            pB[mt] = fmaf(g2, w0, fmaf(g3, w1, pB[mt]));
        }
        pA[mt] += __shfl_xor_sync(0xffffffffu, pA[mt], 1);
        pA[mt] += __shfl_xor_sync(0xffffffffu, pA[mt], 2);
        pB[mt] += __shfl_xor_sync(0xffffffffu, pB[mt], 1);
        pB[mt] += __shfl_xor_sync(0xffffffffu, pB[mt], 2);
        if (t4 == 0) {
            red_s[(m0 + 16 * mt + g4) * 2 + (w >> 2)] = pA[mt];
            red_s[(m0 + 16 * mt + g4 + 8) * 2 + (w >> 2)] = pB[mt];
        }
    }
    __syncthreads();
    if (tid < 128) {
        float s = red_s[tid * 2] + red_s[tid * 2 + 1] + bx2[0];
        float cw = tanhf(s);
        int d = dst_s[tid];
        red_add_f(g_coord + (size_t)d * 3 + 0, diff_s[tid * 3 + 0] * cw);
        red_add_f(g_coord + (size_t)d * 3 + 1, diff_s[tid * 3 + 1] * cw);
        red_add_f(g_coord + (size_t)d * 3 + 2, diff_s[tid * 3 + 2] * cw);
        red_add_f(g_deg + d, 1.0f);
    }
}

// =====================================================================
// Kernel C: node update (tensor-core tf32)
// =====================================================================
__global__ __launch_bounds__(256, 1) void kC(const float* __restrict__ h,
                                             const float* __restrict__ Wh1,
                                             const float* __restrict__ bh1,
                                             const float* __restrict__ Wh2,
                                             const float* __restrict__ bh2,
                                             float* __restrict__ out) {
    extern __shared__ float sm[];
    uint32_t* Hs = (uint32_t*)sm;         // 128*ASTR tf32 bits
    uint32_t* Ws = Hs + 128 * ASTR;       // 128*WSTR tf32 bits
    int tid = threadIdx.x;
    int lane = tid & 31, w = tid >> 5;
    int g4 = lane >> 2, t4 = lane & 3;
    int m0 = (w & 3) * 32, n0 = (w >> 2) * 64;
    int tile0 = blockIdx.x * 128;

    float acc[2][8][4];
#pragma unroll
    for (int mt = 0; mt < 2; mt++)
#pragma unroll
        for (int j = 0; j < 8; j++)
#pragma unroll
            for (int q = 0; q < 4; q++) acc[mt][j][q] = 0.f;

    for (int pass = 0; pass < 2; pass++) {
        const float* src = pass ? (const float*)g_msg4 : h;
        if (pass) __syncthreads();   // previous GEMM reads complete
        {
            int n = tid >> 1, k0l = (tid & 1) * 64;
            int gn = tile0 + n;
#pragma unroll
            for (int q = 0; q < 16; q++) {
                float4 v = make_float4(0.f, 0.f, 0.f, 0.f);
                if (gn < NN) v = *(const float4*)(src + (size_t)gn * 128 + k0l + q * 4);
                uint32_t* p = Hs + (size_t)n * ASTR + k0l + q * 4;
                p[0] = f2tf(v.x); p[1] = f2tf(v.y); p[2] = f2tf(v.z); p[3] = f2tf(v.w);
            }
        }
        stage_w(Wh1 + (size_t)pass * 128 * 128, Ws, tid);
        __syncthreads();
        mma_gemm<false>(Hs, Ws, 128, m0, n0, g4, t4, acc);
    }

    // g = silu(acc + bh1) -> Hs (tf32 bits)
    __syncthreads();
#pragma unroll
    for (int mt = 0; mt < 2; mt++) {
        int rA = m0 + 16 * mt + g4;
#pragma unroll
        for (int j = 0; j < 8; j++) {
            int c = n0 + 8 * j + 2 * t4;
            float2 bb = *(const float2*)(bh1 + c);
            Hs[(size_t)rA * ASTR + c]       = f2tf(silu_f(acc[mt][j][0] + bb.x));
            Hs[(size_t)rA * ASTR + c + 1]   = f2tf(silu_f(acc[mt][j][1] + bb.y));
            Hs[(size_t)(rA + 8) * ASTR + c]     = f2tf(silu_f(acc[mt][j][2] + bb.x));
            Hs[(size_t)(rA + 8) * ASTR + c + 1] = f2tf(silu_f(acc[mt][j][3] + bb.y));
        }
    }
    stage_w(Wh2, Ws, tid);
    __syncthreads();

#pragma unroll
    for (int mt = 0; mt < 2; mt++)
#pragma unroll
        for (int j = 0; j < 8; j++)
#pragma unroll
            for (int q = 0; q < 4; q++) acc[mt][j][q] = 0.f;
    mma_gemm<false>(Hs, Ws, 128, m0, n0, g4, t4, acc);

    // out = h + acc + bh2
#pragma unroll
    for (int mt = 0; mt < 2; mt++) {
        int rA = m0 + 16 * mt + g4;
        int gnA = tile0 + rA, gnB = gnA + 8;
#pragma unroll
        for (int j = 0; j < 8; j++) {
            int c = n0 + 8 * j + 2 * t4;
            float2 bb = *(const float2*)(bh2 + c);
            if (gnA < NN) {
                float2 hv = *(const float2*)(h + (size_t)gnA * 128 + c);
                *(float2*)(out + (size_t)gnA * 128 + c) =
                    make_float2(hv.x + acc[mt][j][0] + bb.x,
                                hv.y + acc[mt][j][1] + bb.y);
            }
            if (gnB < NN) {
                float2 hv = *(const float2*)(h + (size_t)gnB * 128 + c);
                *(float2*)(out + (size_t)gnB * 128 + c) =
                    make_float2(hv.x + acc[mt][j][2] + bb.x,
                                hv.y + acc[mt][j][3] + bb.y);
            }
        }
    }
}

// ---- x_out ----
__global__ void kX(const float* __restrict__ x, float* __restrict__ out) {
    int n = blockIdx.x * blockDim.x + threadIdx.x;
    if (n < NN) {
        float inv = 1.f / (g_deg[n] + 1.f);
        float* o = out + (size_t)NN * 128 + (size_t)n * 3;
        o[0] = x[n * 3 + 0] + g_coord[n * 3 + 0] * inv;
        o[1] = x[n * 3 + 1] + g_coord[n * 3 + 1] * inv;
        o[2] = x[n * 3 + 2] + g_coord[n * 3 + 2] * inv;
    }
}

extern "C" void kernel_launch(void* const* d_in, const int* in_sizes, int n_in,
                              void* d_out, int out_size) {
    const float* h    = (const float*)d_in[0];
    const float* x    = (const float*)d_in[1];
    const float* ea   = (const float*)d_in[2];
    const float* temb = (const float*)d_in[3];
    const float* We1w = (const float*)d_in[4];
    const float* We1b = (const float*)d_in[5];
    const float* We2w = (const float*)d_in[6];
    const float* We2b = (const float*)d_in[7];
    const float* Wattw = (const float*)d_in[8];
    const float* Wattb = (const float*)d_in[9];
    const float* Wx1w = (const float*)d_in[10];
    const float* Wx1b = (const float*)d_in[11];
    const float* Wx2w = (const float*)d_in[12];
    const float* Wx2b = (const float*)d_in[13];
    const float* Wh1w = (const float*)d_in[14];
    const float* Wh1b = (const float*)d_in[15];
    const float* Wh2w = (const float*)d_in[16];
    const float* Wh2b = (const float*)d_in[17];
    const int*   eidx = (const int*)d_in[18];
    float* out = (float*)d_out;

    const int smA = (128 * ASTR + 64 * ASTR + 128 * 128) * 4;
    const int smB = (128 * ASTR + 128 * WSTR + 8 * 128 + 256 +
                     7 * 128 + 128 * 3 + 256) * 4;
    const int smC = (128 * ASTR + 128 * WSTR) * 4;
    cudaFuncSetAttribute(kA, cudaFuncAttributeMaxDynamicSharedMemorySize, smA);
    cudaFuncSetAttribute(kB, cudaFuncAttributeMaxDynamicSharedMemorySize, smB);
    cudaFuncSetAttribute(kC, cudaFuncAttributeMaxDynamicSharedMemorySize, smC);

    kZero<<<4096, 256>>>();
    kA<<<(NN + 127) / 128, 256, smA>>>(h, temb, We1w, We1b);
    kB<<<EE / 128, 256, smB>>>(x, ea, eidx, We1w, We2w, We2b,
                               Wattw, Wattb, Wx1w, Wx1b, Wx2w, Wx2b);
    kC<<<(NN + 127) / 128, 256, smC>>>(h, Wh1w, Wh1b, Wh2w, Wh2b, out);
    kX<<<(NN + 255) / 256, 256>>>(x, out);
}

// round 5
// speedup vs baseline: 2.4146x; 1.3854x over previous
#include <cuda_runtime.h>
#include <cuda_fp16.h>
#include <math.h>
#include <stdint.h>

#define NN 50000
#define EE 800000
#define ASTR 132   // fp32 A-tile stride (kA only)
#define HSTR 136   // fp16 A-tile stride (halves)
#define KSTR 136   // fp16 B-tile stride (halves)

// ---- static device scratch ----
__device__ float4 g_Psrc4[NN * 32];
__device__ float4 g_Pdst4[NN * 32];
__device__ float4 g_msg4 [NN * 32];
__device__ float  g_coord[NN * 3];
__device__ float  g_deg  [NN];
// pre-transposed fp16 weights: [n][k] row-major
__device__ __half g_We2h[128 * 128];
__device__ __half g_Wx1h[128 * 128];
__device__ __half g_Wh1h[128 * 256];
__device__ __half g_Wh2h[128 * 128];

__device__ __forceinline__ float silu_f(float v) {
    return v / (1.f + __expf(-v));
}
__device__ __forceinline__ void red_add_v4(float* p, float a, float b, float c, float d) {
    asm volatile("red.global.add.v4.f32 [%0], {%1,%2,%3,%4};"
                 :: "l"(p), "f"(a), "f"(b), "f"(c), "f"(d) : "memory");
}
__device__ __forceinline__ void red_add_f(float* p, float a) {
    asm volatile("red.global.add.f32 [%0], %1;" :: "l"(p), "f"(a) : "memory");
}
__device__ __forceinline__ uint32_t packh2(float a, float b) {
    __half2 h = __floats2half2_rn(a, b);
    return *(uint32_t*)&h;
}
__device__ __forceinline__ void mma_f16(float c[4], const uint32_t a[4], const uint32_t b[2]) {
    asm volatile("mma.sync.aligned.m16n8k16.row.col.f32.f16.f16.f32 "
                 "{%0,%1,%2,%3}, {%4,%5,%6,%7}, {%8,%9}, {%0,%1,%2,%3};"
                 : "+f"(c[0]), "+f"(c[1]), "+f"(c[2]), "+f"(c[3])
                 : "r"(a[0]), "r"(a[1]), "r"(a[2]), "r"(a[3]),
                   "r"(b[0]), "r"(b[1]));
}

// stage pre-transposed fp16 weight [128][srcK] slice -> smem [n][KSTR]
__device__ __forceinline__ void stage_wt(const __half* __restrict__ src, int srcK,
                                         int kOff, uint16_t* __restrict__ WsB, int tid) {
    int n = tid >> 1, kh = (tid & 1) * 64;
    const uint16_t* s = (const uint16_t*)src + (size_t)n * srcK + kOff + kh;
    uint16_t* d = WsB + n * KSTR + kh;
#pragma unroll
    for (int q = 0; q < 8; q++)
        *(uint4*)(d + 8 * q) = *(const uint4*)(s + 8 * q);
}

// warp fp16 GEMM: C[32x64 per warp] += A[128xK] * B[KxN], K mult of 16
__device__ __forceinline__ void mma_gemm16(const uint16_t* __restrict__ Hs,
                                           const uint16_t* __restrict__ Ws,
                                           int K, int m0, int n0, int g4, int t4,
                                           float acc[2][8][4]) {
#pragma unroll
    for (int k0 = 0; k0 < K; k0 += 16) {
        uint32_t b[8][2];
#pragma unroll
        for (int j = 0; j < 8; j++) {
            const uint16_t* wp = Ws + (n0 + 8 * j + g4) * KSTR + k0 + 2 * t4;
            b[j][0] = *(const uint32_t*)wp;
            b[j][1] = *(const uint32_t*)(wp + 8);
        }
#pragma unroll
        for (int mt = 0; mt < 2; mt++) {
            const uint16_t* ap  = Hs + (m0 + 16 * mt + g4) * HSTR + k0 + 2 * t4;
            const uint16_t* ap8 = ap + 8 * HSTR;
            uint32_t a[4];
            a[0] = *(const uint32_t*)ap;
            a[1] = *(const uint32_t*)ap8;
            a[2] = *(const uint32_t*)(ap + 8);
            a[3] = *(const uint32_t*)(ap8 + 8);
#pragma unroll
            for (int j = 0; j < 8; j++) mma_f16(acc[mt][j], a, b[j]);
        }
    }
}

// ---- zero accumulators ----
__global__ void kZero() {
    float* msg = (float*)g_msg4;
    long total = (long)NN * 128 + NN * 3 + NN;
    for (long i = blockIdx.x * (long)blockDim.x + threadIdx.x; i < total;
         i += (long)gridDim.x * blockDim.x) {
        if (i < (long)NN * 128)             msg[i] = 0.f;
        else if (i < (long)NN * 128 + NN*3) g_coord[i - (long)NN * 128] = 0.f;
        else                                g_deg[i - (long)NN * 128 - NN * 3] = 0.f;
    }
}

// ---- weight transpose + fp16 convert (once per launch) ----
__global__ void kW(const float* __restrict__ We2, const float* __restrict__ Wx1,
                   const float* __restrict__ Wh1, const float* __restrict__ Wh2) {
    int i = blockIdx.x * blockDim.x + threadIdx.x;
    if (i < 16384) {
        int n = i >> 7, k = i & 127;
        g_We2h[i] = __float2half_rn(We2[k * 128 + n]);
        g_Wx1h[i] = __float2half_rn(Wx1[k * 128 + n]);
        g_Wh2h[i] = __float2half_rn(Wh2[k * 128 + n]);
    } else if (i < 16384 + 32768) {
        int j = i - 16384;
        int n = j >> 8, k = j & 255;
        g_Wh1h[j] = __float2half_rn(Wh1[k * 128 + n]);
    }
}

// ---- fp32 GEMM micro-kernel (kA only) ----
__device__ __forceinline__ void gemm_step(const float* __restrict__ As,
                                          const float* __restrict__ Ws,
                                          int K, int tx, int ty, float acc[8][8]) {
#pragma unroll 4
    for (int k = 0; k < K; k++) {
        const float4 a0 = *(const float4*)(As + k * ASTR + ty * 8);
        const float4 a1 = *(const float4*)(As + k * ASTR + ty * 8 + 4);
        const float4 b0 = *(const float4*)(Ws + k * 128 + tx * 8);
        const float4 b1 = *(const float4*)(Ws + k * 128 + tx * 8 + 4);
        float a[8] = {a0.x, a0.y, a0.z, a0.w, a1.x, a1.y, a1.z, a1.w};
        float b[8] = {b0.x, b0.y, b0.z, b0.w, b1.x, b1.y, b1.z, b1.w};
#pragma unroll
        for (int i = 0; i < 8; i++)
#pragma unroll
            for (int j = 0; j < 8; j++)
                acc[i][j] = fmaf(a[i], b[j], acc[i][j]);
    }
}

// =====================================================================
// Kernel A: per-node precompute (fp32)
// =====================================================================
__global__ __launch_bounds__(256, 1) void kA(const float* __restrict__ h,
                                             const float* __restrict__ t_emb,
                                             const float* __restrict__ We1,
                                             const float* __restrict__ be1) {
    extern __shared__ float sm[];
    float* As = sm;
    float* Ts = As + 128 * ASTR;
    float* Ws = Ts + 64 * ASTR;
    int tid = threadIdx.x;
    int tx = tid & 15, ty = tid >> 4;
    int tile0 = blockIdx.x * 128;

    {
        int n = tid & 127;
        int gn = tile0 + n;
        int kh = (tid >> 7) * 64;
#pragma unroll
        for (int q = 0; q < 16; q++) {
            int k = kh + q * 4;
            float4 v = make_float4(0.f, 0.f, 0.f, 0.f);
            if (gn < NN) v = *(const float4*)(h + (size_t)gn * 128 + k);
            As[(k + 0) * ASTR + n] = v.x; As[(k + 1) * ASTR + n] = v.y;
            As[(k + 2) * ASTR + n] = v.z; As[(k + 3) * ASTR + n] = v.w;
        }
        int kt = (tid >> 7) * 32;
#pragma unroll
        for (int q = 0; q < 8; q++) {
            int k = kt + q * 4;
            float4 v = make_float4(0.f, 0.f, 0.f, 0.f);
            if (gn < NN) v = *(const float4*)(t_emb + (size_t)gn * 64 + k);
            Ts[(k + 0) * ASTR + n] = v.x; Ts[(k + 1) * ASTR + n] = v.y;
            Ts[(k + 2) * ASTR + n] = v.z; Ts[(k + 3) * ASTR + n] = v.w;
        }
    }
#pragma unroll
    for (int i = 0; i < 16; i++) {
        int fi = i * 256 + tid;
        ((float4*)Ws)[fi] = ((const float4*)We1)[fi];
    }
    __syncthreads();

    float acc[8][8];
#pragma unroll
    for (int i = 0; i < 8; i++)
#pragma unroll
        for (int j = 0; j < 8; j++) acc[i][j] = 0.f;
    gemm_step(As, Ws, 128, tx, ty, acc);
    __syncthreads();

#pragma unroll
    for (int i = 0; i < 8; i++) {
        int fi = i * 256 + tid;
        ((float4*)Ws)[fi] = ((const float4*)(We1 + 265 * 128))[fi];
    }
    __syncthreads();
    gemm_step(Ts, Ws, 64, tx, ty, acc);

    {
        float4 b0 = *(const float4*)(be1 + tx * 8);
        float4 b1 = *(const float4*)(be1 + tx * 8 + 4);
        float bb[8] = {b0.x, b0.y, b0.z, b0.w, b1.x, b1.y, b1.z, b1.w};
        float* Psrc = (float*)g_Psrc4;
#pragma unroll
        for (int i = 0; i < 8; i++) {
            int gn = tile0 + ty * 8 + i;
            if (gn < NN) {
                *(float4*)(Psrc + (size_t)gn * 128 + tx * 8) =
                    make_float4(acc[i][0] + bb[0], acc[i][1] + bb[1],
                                acc[i][2] + bb[2], acc[i][3] + bb[3]);
                *(float4*)(Psrc + (size_t)gn * 128 + tx * 8 + 4) =
                    make_float4(acc[i][4] + bb[4], acc[i][5] + bb[5],
                                acc[i][6] + bb[6], acc[i][7] + bb[7]);
            }
        }
    }
    __syncthreads();

#pragma unroll
    for (int i = 0; i < 16; i++) {
        int fi = i * 256 + tid;
        ((float4*)Ws)[fi] = ((const float4*)(We1 + 128 * 128))[fi];
    }
    __syncthreads();
#pragma unroll
    for (int i = 0; i < 8; i++)
#pragma unroll
        for (int j = 0; j < 8; j++) acc[i][j] = 0.f;
    gemm_step(As, Ws, 128, tx, ty, acc);
    {
        float* Pdst = (float*)g_Pdst4;
#pragma unroll
        for (int i = 0; i < 8; i++) {
            int gn = tile0 + ty * 8 + i;
            if (gn < NN) {
                *(float4*)(Pdst + (size_t)gn * 128 + tx * 8) =
                    make_float4(acc[i][0], acc[i][1], acc[i][2], acc[i][3]);
                *(float4*)(Pdst + (size_t)gn * 128 + tx * 8 + 4) =
                    make_float4(acc[i][4], acc[i][5], acc[i][6], acc[i][7]);
            }
        }
    }
}

// =====================================================================
// Kernel B: fused edge pipeline (fp16 mma), 128 edges per block
// =====================================================================
__global__ __launch_bounds__(256, 2) void kB(const float* __restrict__ x,
                                             const float* __restrict__ ea,
                                             const int* __restrict__ eidx,
                                             const float* __restrict__ We1,
                                             const float* __restrict__ be2,
                                             const float* __restrict__ Watt,
                                             const float* __restrict__ batt,
                                             const float* __restrict__ bx1,
                                             const float* __restrict__ Wx2,
                                             const float* __restrict__ bx2) {
    extern __shared__ float sm[];
    uint16_t* HsB = (uint16_t*)sm;              // 128*HSTR halves
    uint16_t* WsB = HsB + 128 * HSTR;           // 128*KSTR halves
    float* we1e  = (float*)(WsB + 128 * KSTR);  // 1024
    float* red_s = we1e + 1024;                 // 256
    float* wd_s  = red_s + 256;                 // 128
    float* watt_s = wd_s + 128;                 // 128
    float* be2_s  = watt_s + 128;               // 128
    float* bx1_s  = be2_s + 128;                // 128
    float* wx2_s  = bx1_s + 128;                // 128
    float* att_s  = wx2_s + 128;                // 128
    float* dsq_s  = att_s + 128;                // 128
    float* diff_s = dsq_s + 128;                // 384
    int* src_s = (int*)(diff_s + 384);          // 128
    int* dst_s = src_s + 128;                   // 128

    int tid = threadIdx.x;
    int lane = tid & 31, w = tid >> 5;
    int g4 = lane >> 2, t4 = lane & 3;
    int m0 = (w & 3) * 32, n0 = (w >> 2) * 64;
    int e0 = blockIdx.x * 128;

    if (tid < 128) {
        int e = e0 + tid;
        int s = eidx[e], d = eidx[EE + e];
        src_s[tid] = s; dst_s[tid] = d;
        float dx = x[s * 3 + 0] - x[d * 3 + 0];
        float dy = x[s * 3 + 1] - x[d * 3 + 1];
        float dz = x[s * 3 + 2] - x[d * 3 + 2];
        diff_s[tid * 3 + 0] = dx; diff_s[tid * 3 + 1] = dy; diff_s[tid * 3 + 2] = dz;
        dsq_s[tid] = dx * dx + dy * dy + dz * dz;
        wd_s[tid]   = We1[256 * 128 + tid];
        watt_s[tid] = Watt[tid];
        be2_s[tid]  = be2[tid];
        bx1_s[tid]  = bx1[tid];
        wx2_s[tid]  = Wx2[tid];
    }
    ((float4*)we1e)[tid] = ((const float4*)(We1 + 257 * 128))[tid];
    stage_wt(g_We2h, 128, 0, WsB, tid);
    __syncthreads();

    {   // hidden = silu(Psrc[src]+Pdst[dst]+dsq*wd+ea@We1e) -> HsB fp16 [e][j]
        int e = tid >> 1;
        int j0 = (tid & 1) * 64;
        int s = src_s[e], d = dst_s[e];
        float dsq = dsq_s[e];
        float4 e0v = *(const float4*)(ea + (size_t)(e0 + e) * 8);
        float4 e1v = *(const float4*)(ea + (size_t)(e0 + e) * 8 + 4);
        float ear[8] = {e0v.x, e0v.y, e0v.z, e0v.w, e1v.x, e1v.y, e1v.z, e1v.w};
        const float4* ps = (const float4*)((float*)g_Psrc4 + (size_t)s * 128 + j0);
        const float4* pd = (const float4*)((float*)g_Pdst4 + (size_t)d * 128 + j0);
#pragma unroll
        for (int q = 0; q < 16; q++) {
            float4 a = ps[q], b = pd[q];
            int j = j0 + q * 4;
            float4 wv = *(const float4*)(wd_s + j);
            float p0 = fmaf(dsq, wv.x, a.x + b.x);
            float p1 = fmaf(dsq, wv.y, a.y + b.y);
            float p2 = fmaf(dsq, wv.z, a.z + b.z);
            float p3 = fmaf(dsq, wv.w, a.w + b.w);
#pragma unroll
            for (int tt = 0; tt < 8; tt++) {
                float4 we = *(const float4*)(we1e + tt * 128 + j);
                p0 = fmaf(ear[tt], we.x, p0);
                p1 = fmaf(ear[tt], we.y, p1);
                p2 = fmaf(ear[tt], we.z, p2);
                p3 = fmaf(ear[tt], we.w, p3);
            }
            uint32_t u01 = packh2(silu_f(p0), silu_f(p1));
            uint32_t u23 = packh2(silu_f(p2), silu_f(p3));
            *(uint2*)(HsB + (size_t)e * HSTR + j) = make_uint2(u01, u23);
        }
    }
    __syncthreads();

    // GEMM1: m = hidden @ We2
    float acc[2][8][4];
#pragma unroll
    for (int mt = 0; mt < 2; mt++)
#pragma unroll
        for (int j = 0; j < 8; j++)
#pragma unroll
            for (int q = 0; q < 4; q++) acc[mt][j][q] = 0.f;
    mma_gemm16(HsB, WsB, 128, m0, n0, g4, t4, acc);

    // epilogue1: bias + att partial dot
    float pA[2], pB[2];
#pragma unroll
    for (int mt = 0; mt < 2; mt++) {
        pA[mt] = 0.f; pB[mt] = 0.f;
#pragma unroll
        for (int j = 0; j < 8; j++) {
            int c = n0 + 8 * j + 2 * t4;
            float b0 = be2_s[c], b1 = be2_s[c + 1];
            float w0 = watt_s[c], w1 = watt_s[c + 1];
            acc[mt][j][0] += b0; acc[mt][j][1] += b1;
            acc[mt][j][2] += b0; acc[mt][j][3] += b1;
            pA[mt] = fmaf(acc[mt][j][0], w0, fmaf(acc[mt][j][1], w1, pA[mt]));
            pB[mt] = fmaf(acc[mt][j][2], w0, fmaf(acc[mt][j][3], w1, pB[mt]));
        }
        pA[mt] += __shfl_xor_sync(0xffffffffu, pA[mt], 1);
        pA[mt] += __shfl_xor_sync(0xffffffffu, pA[mt], 2);
        pB[mt] += __shfl_xor_sync(0xffffffffu, pB[mt], 1);
        pB[mt] += __shfl_xor_sync(0xffffffffu, pB[mt], 2);
        if (t4 == 0) {
            red_s[(m0 + 16 * mt + g4) * 2 + (w >> 2)] = pA[mt];
            red_s[(m0 + 16 * mt + g4 + 8) * 2 + (w >> 2)] = pB[mt];
        }
    }
    __syncthreads();
    if (tid < 128) {
        float s = red_s[tid * 2] + red_s[tid * 2 + 1] + batt[0];
        att_s[tid] = 1.f / (1.f + __expf(-s));
    }
    __syncthreads();

    // gate + store m (fp16) into HsB; stage Wx1
#pragma unroll
    for (int mt = 0; mt < 2; mt++) {
        int rA = m0 + 16 * mt + g4;
        float aA = att_s[rA], aB = att_s[rA + 8];
#pragma unroll
        for (int j = 0; j < 8; j++) {
            int c = n0 + 8 * j + 2 * t4;
            *(uint32_t*)(HsB + (size_t)rA * HSTR + c) =
                packh2(acc[mt][j][0] * aA, acc[mt][j][1] * aA);
            *(uint32_t*)(HsB + (size_t)(rA + 8) * HSTR + c) =
                packh2(acc[mt][j][2] * aB, acc[mt][j][3] * aB);
        }
    }
    stage_wt(g_Wx1h, 128, 0, WsB, tid);
    __syncthreads();

    // scatter msg_agg from HsB (fp16 m)
    {
        int r = tid >> 1, j0 = (tid & 1) * 64;
        int d = dst_s[r];
        const uint16_t* hp = HsB + (size_t)r * HSTR + j0;
        float* p = (float*)g_msg4 + (size_t)d * 128 + j0;
#pragma unroll
        for (int q = 0; q < 8; q++) {
            uint4 raw = *(const uint4*)(hp + 8 * q);
            float2 f0 = __half22float2(*(__half2*)&raw.x);
            float2 f1 = __half22float2(*(__half2*)&raw.y);
            float2 f2 = __half22float2(*(__half2*)&raw.z);
            float2 f3 = __half22float2(*(__half2*)&raw.w);
            red_add_v4(p + 8 * q,     f0.x, f0.y, f1.x, f1.y);
            red_add_v4(p + 8 * q + 4, f2.x, f2.y, f3.x, f3.y);
        }
    }

    // GEMM2: g = silu(m @ Wx1 + bx1); coordw partial = g @ Wx2
#pragma unroll
    for (int mt = 0; mt < 2; mt++)
#pragma unroll
        for (int j = 0; j < 8; j++)
#pragma unroll
            for (int q = 0; q < 4; q++) acc[mt][j][q] = 0.f;
    mma_gemm16(HsB, WsB, 128, m0, n0, g4, t4, acc);

#pragma unroll
    for (int mt = 0; mt < 2; mt++) {
        pA[mt] = 0.f; pB[mt] = 0.f;
#pragma unroll
        for (int j = 0; j < 8; j++) {
            int c = n0 + 8 * j + 2 * t4;
            float b0 = bx1_s[c], b1 = bx1_s[c + 1];
            float w0 = wx2_s[c], w1 = wx2_s[c + 1];
            float g0 = silu_f(acc[mt][j][0] + b0);
            float g1 = silu_f(acc[mt][j][1] + b1);
            float g2 = silu_f(acc[mt][j][2] + b0);
            float g3 = silu_f(acc[mt][j][3] + b1);
            pA[mt] = fmaf(g0, w0, fmaf(g1, w1, pA[mt]));
            pB[mt] = fmaf(g2, w0, fmaf(g3, w1, pB[mt]));
        }
        pA[mt] += __shfl_xor_sync(0xffffffffu, pA[mt], 1);
        pA[mt] += __shfl_xor_sync(0xffffffffu, pA[mt], 2);
        pB[mt] += __shfl_xor_sync(0xffffffffu, pB[mt], 1);
        pB[mt] += __shfl_xor_sync(0xffffffffu, pB[mt], 2);
        if (t4 == 0) {
            red_s[(m0 + 16 * mt + g4) * 2 + (w >> 2)] = pA[mt];
            red_s[(m0 + 16 * mt + g4 + 8) * 2 + (w >> 2)] = pB[mt];
        }
    }
    __syncthreads();
    if (tid < 128) {
        float s = red_s[tid * 2] + red_s[tid * 2 + 1] + bx2[0];
        float cw = tanhf(s);
        int d = dst_s[tid];
        red_add_f(g_coord + (size_t)d * 3 + 0, diff_s[tid * 3 + 0] * cw);
        red_add_f(g_coord + (size_t)d * 3 + 1, diff_s[tid * 3 + 1] * cw);
        red_add_f(g_coord + (size_t)d * 3 + 2, diff_s[tid * 3 + 2] * cw);
        red_add_f(g_deg + d, 1.0f);
    }
}

// =====================================================================
// Kernel C: node update (fp16 mma)
// =====================================================================
__global__ __launch_bounds__(256, 2) void kC(const float* __restrict__ h,
                                             const float* __restrict__ bh1,
                                             const float* __restrict__ bh2,
                                             float* __restrict__ out) {
    extern __shared__ float sm[];
    uint16_t* HsB = (uint16_t*)sm;
    uint16_t* WsB = HsB + 128 * HSTR;
    int tid = threadIdx.x;
    int lane = tid & 31, w = tid >> 5;
    int g4 = lane >> 2, t4 = lane & 3;
    int m0 = (w & 3) * 32, n0 = (w >> 2) * 64;
    int tile0 = blockIdx.x * 128;

    float acc[2][8][4];
#pragma unroll
    for (int mt = 0; mt < 2; mt++)
#pragma unroll
        for (int j = 0; j < 8; j++)
#pragma unroll
            for (int q = 0; q < 4; q++) acc[mt][j][q] = 0.f;

    for (int pass = 0; pass < 2; pass++) {
        const float* src = pass ? (const float*)g_msg4 : h;
        if (pass) __syncthreads();
        {   // stage A tile fp16
            int n = tid >> 1, kh = (tid & 1) * 64;
            int gn = tile0 + n;
            uint16_t* d = HsB + (size_t)n * HSTR + kh;
#pragma unroll
            for (int q = 0; q < 8; q++) {
                float4 v0 = make_float4(0.f, 0.f, 0.f, 0.f);
                float4 v1 = make_float4(0.f, 0.f, 0.f, 0.f);
                if (gn < NN) {
                    v0 = *(const float4*)(src + (size_t)gn * 128 + kh + q * 8);
                    v1 = *(const float4*)(src + (size_t)gn * 128 + kh + q * 8 + 4);
                }
                uint4 u;
                u.x = packh2(v0.x, v0.y); u.y = packh2(v0.z, v0.w);
                u.z = packh2(v1.x, v1.y); u.w = packh2(v1.z, v1.w);
                *(uint4*)(d + 8 * q) = u;
            }
        }
        stage_wt(g_Wh1h, 256, pass * 128, WsB, tid);
        __syncthreads();
        mma_gemm16(HsB, WsB, 128, m0, n0, g4, t4, acc);
    }

    // g = silu(acc + bh1) -> HsB fp16
    __syncthreads();
#pragma unroll
    for (int mt = 0; mt < 2; mt++) {
        int rA = m0 + 16 * mt + g4;
#pragma unroll
        for (int j = 0; j < 8; j++) {
            int c = n0 + 8 * j + 2 * t4;
            float2 bb = *(const float2*)(bh1 + c);
            *(uint32_t*)(HsB + (size_t)rA * HSTR + c) =
                packh2(silu_f(acc[mt][j][0] + bb.x), silu_f(acc[mt][j][1] + bb.y));
            *(uint32_t*)(HsB + (size_t)(rA + 8) * HSTR + c) =
                packh2(silu_f(acc[mt][j][2] + bb.x), silu_f(acc[mt][j][3] + bb.y));
        }
    }
    stage_wt(g_Wh2h, 128, 0, WsB, tid);
    __syncthreads();

#pragma unroll
    for (int mt = 0; mt < 2; mt++)
#pragma unroll
        for (int j = 0; j < 8; j++)
#pragma unroll
            for (int q = 0; q < 4; q++) acc[mt][j][q] = 0.f;
    mma_gemm16(HsB, WsB, 128, m0, n0, g4, t4, acc);

    // out = h + acc + bh2
#pragma unroll
    for (int mt = 0; mt < 2; mt++) {
        int rA = m0 + 16 * mt + g4;
        int gnA = tile0 + rA, gnB = gnA + 8;
#pragma unroll
        for (int j = 0; j < 8; j++) {
            int c = n0 + 8 * j + 2 * t4;
            float2 bb = *(const float2*)(bh2 + c);
            if (gnA < NN) {
                float2 hv = *(const float2*)(h + (size_t)gnA * 128 + c);
                *(float2*)(out + (size_t)gnA * 128 + c) =
                    make_float2(hv.x + acc[mt][j][0] + bb.x,
                                hv.y + acc[mt][j][1] + bb.y);
            }
            if (gnB < NN) {
                float2 hv = *(const float2*)(h + (size_t)gnB * 128 + c);
                *(float2*)(out + (size_t)gnB * 128 + c) =
                    make_float2(hv.x + acc[mt][j][2] + bb.x,
                                hv.y + acc[mt][j][3] + bb.y);
            }
        }
    }
}

// ---- x_out ----
__global__ void kX(const float* __restrict__ x, float* __restrict__ out) {
    int n = blockIdx.x * blockDim.x + threadIdx.x;
    if (n < NN) {
        float inv = 1.f / (g_deg[n] + 1.f);
        float* o = out + (size_t)NN * 128 + (size_t)n * 3;
        o[0] = x[n * 3 + 0] + g_coord[n * 3 + 0] * inv;
        o[1] = x[n * 3 + 1] + g_coord[n * 3 + 1] * inv;
        o[2] = x[n * 3 + 2] + g_coord[n * 3 + 2] * inv;
    }
}

extern "C" void kernel_launch(void* const* d_in, const int* in_sizes, int n_in,
                              void* d_out, int out_size) {
    const float* h    = (const float*)d_in[0];
    const float* x    = (const float*)d_in[1];
    const float* ea   = (const float*)d_in[2];
    const float* temb = (const float*)d_in[3];
    const float* We1w = (const float*)d_in[4];
    const float* We1b = (const float*)d_in[5];
    const float* We2w = (const float*)d_in[6];
    const float* We2b = (const float*)d_in[7];
    const float* Wattw = (const float*)d_in[8];
    const float* Wattb = (const float*)d_in[9];
    const float* Wx1w = (const float*)d_in[10];
    const float* Wx1b = (const float*)d_in[11];
    const float* Wx2w = (const float*)d_in[12];
    const float* Wx2b = (const float*)d_in[13];
    const float* Wh1w = (const float*)d_in[14];
    const float* Wh1b = (const float*)d_in[15];
    const float* Wh2w = (const float*)d_in[16];
    const float* Wh2b = (const float*)d_in[17];
    const int*   eidx = (const int*)d_in[18];
    float* out = (float*)d_out;

    const int smA = (128 * ASTR + 64 * ASTR + 128 * 128) * 4;
    // kB float region: we1e 1024 + red 256 + 7*128 scalars + diff 384 = 2560 floats
    // + 256 ints (src/dst) + 512B pad
    const int smB = 128 * HSTR * 2 + 128 * KSTR * 2 +
                    (1024 + 256 + 128 * 7 + 384) * 4 + 256 * 4 + 512;
    const int smC = 128 * HSTR * 2 + 128 * KSTR * 2;
    cudaFuncSetAttribute(kA, cudaFuncAttributeMaxDynamicSharedMemorySize, smA);
    cudaFuncSetAttribute(kB, cudaFuncAttributeMaxDynamicSharedMemorySize, smB);
    cudaFuncSetAttribute(kC, cudaFuncAttributeMaxDynamicSharedMemorySize, smC);

    kZero<<<2048, 256>>>();
    kW<<<(16384 + 32768 + 255) / 256, 256>>>(We2w, Wx1w, Wh1w, Wh2w);
    kA<<<(NN + 127) / 128, 256, smA>>>(h, temb, We1w, We1b);
    kB<<<EE / 128, 256, smB>>>(x, ea, eidx, We1w, We2b,
                               Wattw, Wattb, Wx1b, Wx2w, Wx2b);
    kC<<<(NN + 127) / 128, 256, smC>>>(h, Wh1b, Wh2b, out);
    kX<<<(NN + 255) / 256, 256>>>(x, out);
}

// round 6
// speedup vs baseline: 3.0316x; 1.2556x over previous
#include <cuda_runtime.h>
#include <cuda_fp16.h>
#include <math.h>
#include <stdint.h>

#define NN 50000
#define EE 800000
#define HSTR 136   // fp16 A-tile stride (halves)
#define KSTR 136   // fp16 B-tile stride (halves)
#define ESTR 40    // small edge-feature tile stride (halves): banks r*20+t4 distinct
#define TSTR 72    // t_emb tile stride (halves)

// ---- static device scratch ----
__device__ __half g_Psrch[NN * 128];
__device__ __half g_Pdsth[NN * 128];
__device__ float4 g_msg4 [NN * 32];
__device__ float  g_coord[NN * 3];
__device__ float  g_deg  [NN];
// pre-transposed fp16 weights [n][k]
__device__ __half g_We2h[128 * 128];
__device__ __half g_Wx1h[128 * 128];
__device__ __half g_Wh1h[128 * 256];
__device__ __half g_Wh2h[128 * 128];
__device__ __half g_W1ah[128 * 128];   // We1 rows 0..127   (h_src block)
__device__ __half g_W1bh[128 * 128];   // We1 rows 128..255 (h_dst block)
__device__ __half g_W1th[128 * 64];    // We1 rows 265..328 (t_emb block)
__device__ __half g_WeEh[128 * 16];    // [n][k]: k0=wd, k1..8=We1e, k9..15=0

__device__ __forceinline__ float silu_f(float v) {
    return v / (1.f + __expf(-v));
}
__device__ __forceinline__ void red_add_v4(float* p, float a, float b, float c, float d) {
    asm volatile("red.global.add.v4.f32 [%0], {%1,%2,%3,%4};"
                 :: "l"(p), "f"(a), "f"(b), "f"(c), "f"(d) : "memory");
}
__device__ __forceinline__ void red_add_f(float* p, float a) {
    asm volatile("red.global.add.f32 [%0], %1;" :: "l"(p), "f"(a) : "memory");
}
__device__ __forceinline__ uint32_t packh2(float a, float b) {
    __half2 h = __floats2half2_rn(a, b);
    return *(uint32_t*)&h;
}
__device__ __forceinline__ void mma_f16(float c[4], const uint32_t a[4], const uint32_t b[2]) {
    asm volatile("mma.sync.aligned.m16n8k16.row.col.f32.f16.f16.f32 "
                 "{%0,%1,%2,%3}, {%4,%5,%6,%7}, {%8,%9}, {%0,%1,%2,%3};"
                 : "+f"(c[0]), "+f"(c[1]), "+f"(c[2]), "+f"(c[3])
                 : "r"(a[0]), "r"(a[1]), "r"(a[2]), "r"(a[3]),
                   "r"(b[0]), "r"(b[1]));
}

// stage pre-transposed fp16 weight [128][srcK] slice -> smem [n][KSTR]
__device__ __forceinline__ void stage_wt(const __half* __restrict__ src, int srcK,
                                         int kOff, uint16_t* __restrict__ WsB, int tid) {
    int n = tid >> 1, kh = (tid & 1) * 64;
    const uint16_t* s = (const uint16_t*)src + (size_t)n * srcK + kOff + kh;
    uint16_t* d = WsB + n * KSTR + kh;
#pragma unroll
    for (int q = 0; q < 8; q++)
        *(uint4*)(d + 8 * q) = *(const uint4*)(s + 8 * q);
}
// stage 64-wide fp16 weight [128][64] -> smem [n][KSTR]
__device__ __forceinline__ void stage_wt64(const __half* __restrict__ src,
                                           uint16_t* __restrict__ WsB, int tid) {
    int n = tid >> 1, kh = (tid & 1) * 32;
    const uint16_t* s = (const uint16_t*)src + (size_t)n * 64 + kh;
    uint16_t* d = WsB + n * KSTR + kh;
#pragma unroll
    for (int q = 0; q < 4; q++)
        *(uint4*)(d + 8 * q) = *(const uint4*)(s + 8 * q);
}

// warp fp16 GEMM: C[32x64 per warp] += A[128xK] * B[KxN]^T-stored, K mult of 16
template<int AS, int BS>
__device__ __forceinline__ void mma_gemm16(const uint16_t* __restrict__ Hs,
                                           const uint16_t* __restrict__ Ws,
                                           int K, int m0, int n0, int g4, int t4,
                                           float acc[2][8][4]) {
#pragma unroll
    for (int k0 = 0; k0 < K; k0 += 16) {
        uint32_t b[8][2];
#pragma unroll
        for (int j = 0; j < 8; j++) {
            const uint16_t* wp = Ws + (n0 + 8 * j + g4) * BS + k0 + 2 * t4;
            b[j][0] = *(const uint32_t*)wp;
            b[j][1] = *(const uint32_t*)(wp + 8);
        }
#pragma unroll
        for (int mt = 0; mt < 2; mt++) {
            const uint16_t* ap  = Hs + (m0 + 16 * mt + g4) * AS + k0 + 2 * t4;
            const uint16_t* ap8 = ap + 8 * AS;
            uint32_t a[4];
            a[0] = *(const uint32_t*)ap;
            a[1] = *(const uint32_t*)ap8;
            a[2] = *(const uint32_t*)(ap + 8);
            a[3] = *(const uint32_t*)(ap8 + 8);
#pragma unroll
            for (int j = 0; j < 8; j++) mma_f16(acc[mt][j], a, b[j]);
        }
    }
}

// ---- zero accumulators ----
__global__ void kZero() {
    float* msg = (float*)g_msg4;
    long total = (long)NN * 128 + NN * 3 + NN;
    for (long i = blockIdx.x * (long)blockDim.x + threadIdx.x; i < total;
         i += (long)gridDim.x * blockDim.x) {
        if (i < (long)NN * 128)             msg[i] = 0.f;
        else if (i < (long)NN * 128 + NN*3) g_coord[i - (long)NN * 128] = 0.f;
        else                                g_deg[i - (long)NN * 128 - NN * 3] = 0.f;
    }
}

// ---- weight transpose + fp16 convert (once per launch) ----
__global__ void kW(const float* __restrict__ We1, const float* __restrict__ We2,
                   const float* __restrict__ Wx1,
                   const float* __restrict__ Wh1, const float* __restrict__ Wh2) {
    int i = blockIdx.x * blockDim.x + threadIdx.x;
    if (i < 16384) {
        int n = i >> 7, k = i & 127;
        g_We2h[i] = __float2half_rn(We2[k * 128 + n]);
        g_Wx1h[i] = __float2half_rn(Wx1[k * 128 + n]);
        g_Wh2h[i] = __float2half_rn(Wh2[k * 128 + n]);
    } else if (i < 49152) {
        int j = i - 16384;
        int n = j >> 8, k = j & 255;
        g_Wh1h[j] = __float2half_rn(Wh1[k * 128 + n]);
    } else if (i < 65536) {
        int j = i - 49152;
        int n = j >> 7, k = j & 127;
        g_W1ah[j] = __float2half_rn(We1[k * 128 + n]);
    } else if (i < 81920) {
        int j = i - 65536;
        int n = j >> 7, k = j & 127;
        g_W1bh[j] = __float2half_rn(We1[(128 + k) * 128 + n]);
    } else if (i < 90112) {
        int j = i - 81920;
        int n = j >> 6, k = j & 63;
        g_W1th[j] = __float2half_rn(We1[(265 + k) * 128 + n]);
    } else if (i < 92160) {
        int j = i - 90112;
        int n = j >> 4, k = j & 15;
        float v = 0.f;
        if (k == 0)      v = We1[256 * 128 + n];
        else if (k <= 8) v = We1[(256 + k) * 128 + n];
        g_WeEh[j] = __float2half_rn(v);
    }
}

// =====================================================================
// Kernel A: per-node precompute (fp16 mma)
//   Psrc = h@We1[0:128] + t_emb@We1[265:329] + be1 ; Pdst = h@We1[128:256]
// =====================================================================
__global__ __launch_bounds__(256, 2) void kA(const float* __restrict__ h,
                                             const float* __restrict__ temb,
                                             const float* __restrict__ be1) {
    extern __shared__ float sm[];
    uint16_t* HsB = (uint16_t*)sm;          // 128*HSTR
    uint16_t* WsB = HsB + 128 * HSTR;       // 128*KSTR
    uint16_t* Ts  = WsB + 128 * KSTR;       // 128*TSTR
    int tid = threadIdx.x;
    int lane = tid & 31, w = tid >> 5;
    int g4 = lane >> 2, t4 = lane & 3;
    int m0 = (w & 3) * 32, n0 = (w >> 2) * 64;
    int tile0 = blockIdx.x * 128;

    {   // stage h -> HsB fp16
        int n = tid >> 1, kh = (tid & 1) * 64;
        int gn = tile0 + n;
        uint16_t* d = HsB + (size_t)n * HSTR + kh;
#pragma unroll
        for (int q = 0; q < 8; q++) {
            float4 v0 = make_float4(0.f,0.f,0.f,0.f), v1 = v0;
            if (gn < NN) {
                v0 = *(const float4*)(h + (size_t)gn * 128 + kh + q * 8);
                v1 = *(const float4*)(h + (size_t)gn * 128 + kh + q * 8 + 4);
            }
            uint4 u;
            u.x = packh2(v0.x, v0.y); u.y = packh2(v0.z, v0.w);
            u.z = packh2(v1.x, v1.y); u.w = packh2(v1.z, v1.w);
            *(uint4*)(d + 8 * q) = u;
        }
    }
    {   // stage t_emb -> Ts fp16
        int n = tid >> 1, kh = (tid & 1) * 32;
        int gn = tile0 + n;
        uint16_t* d = Ts + (size_t)n * TSTR + kh;
#pragma unroll
        for (int q = 0; q < 4; q++) {
            float4 v0 = make_float4(0.f,0.f,0.f,0.f), v1 = v0;
            if (gn < NN) {
                v0 = *(const float4*)(temb + (size_t)gn * 64 + kh + q * 8);
                v1 = *(const float4*)(temb + (size_t)gn * 64 + kh + q * 8 + 4);
            }
            uint4 u;
            u.x = packh2(v0.x, v0.y); u.y = packh2(v0.z, v0.w);
            u.z = packh2(v1.x, v1.y); u.w = packh2(v1.z, v1.w);
            *(uint4*)(d + 8 * q) = u;
        }
    }
    stage_wt(g_W1ah, 128, 0, WsB, tid);
    __syncthreads();

    float acc[2][8][4];
#pragma unroll
    for (int mt = 0; mt < 2; mt++)
#pragma unroll
        for (int j = 0; j < 8; j++)
#pragma unroll
            for (int q = 0; q < 4; q++) acc[mt][j][q] = 0.f;
    mma_gemm16<HSTR,KSTR>(HsB, WsB, 128, m0, n0, g4, t4, acc);
    __syncthreads();
    stage_wt64(g_W1th, WsB, tid);
    __syncthreads();
    mma_gemm16<TSTR,KSTR>(Ts, WsB, 64, m0, n0, g4, t4, acc);

    // store Psrc (+be1) as fp16
#pragma unroll
    for (int mt = 0; mt < 2; mt++) {
        int rA = m0 + 16 * mt + g4;
        int gnA = tile0 + rA, gnB = gnA + 8;
#pragma unroll
        for (int j = 0; j < 8; j++) {
            int c = n0 + 8 * j + 2 * t4;
            float2 bb = *(const float2*)(be1 + c);
            if (gnA < NN)
                *(uint32_t*)((uint16_t*)g_Psrch + (size_t)gnA * 128 + c) =
                    packh2(acc[mt][j][0] + bb.x, acc[mt][j][1] + bb.y);
            if (gnB < NN)
                *(uint32_t*)((uint16_t*)g_Psrch + (size_t)gnB * 128 + c) =
                    packh2(acc[mt][j][2] + bb.x, acc[mt][j][3] + bb.y);
        }
    }
    __syncthreads();
    stage_wt(g_W1bh, 128, 0, WsB, tid);
    __syncthreads();
#pragma unroll
    for (int mt = 0; mt < 2; mt++)
#pragma unroll
        for (int j = 0; j < 8; j++)
#pragma unroll
            for (int q = 0; q < 4; q++) acc[mt][j][q] = 0.f;
    mma_gemm16<HSTR,KSTR>(HsB, WsB, 128, m0, n0, g4, t4, acc);
#pragma unroll
    for (int mt = 0; mt < 2; mt++) {
        int rA = m0 + 16 * mt + g4;
        int gnA = tile0 + rA, gnB = gnA + 8;
#pragma unroll
        for (int j = 0; j < 8; j++) {
            int c = n0 + 8 * j + 2 * t4;
            if (gnA < NN)
                *(uint32_t*)((uint16_t*)g_Pdsth + (size_t)gnA * 128 + c) =
                    packh2(acc[mt][j][0], acc[mt][j][1]);
            if (gnB < NN)
                *(uint32_t*)((uint16_t*)g_Pdsth + (size_t)gnB * 128 + c) =
                    packh2(acc[mt][j][2], acc[mt][j][3]);
        }
    }
}

// =====================================================================
// Kernel B: fused edge pipeline, 128 edges per block
// =====================================================================
__global__ __launch_bounds__(256, 2) void kB(const float* __restrict__ x,
                                             const float* __restrict__ ea,
                                             const int* __restrict__ eidx,
                                             const float* __restrict__ be2,
                                             const float* __restrict__ Watt,
                                             const float* __restrict__ batt,
                                             const float* __restrict__ bx1,
                                             const float* __restrict__ Wx2,
                                             const float* __restrict__ bx2) {
    extern __shared__ float sm[];
    uint16_t* HsB = (uint16_t*)sm;              // 128*HSTR
    uint16_t* WsB = HsB + 128 * HSTR;           // 128*KSTR
    uint16_t* Es  = WsB + 128 * KSTR;           // 128*ESTR (edge feats, K=16)
    uint16_t* Wes = Es + 128 * ESTR;            // 128*ESTR
    float* red_s  = (float*)(Wes + 128 * ESTR); // 256
    float* watt_s = red_s + 256;                // 128
    float* be2_s  = watt_s + 128;
    float* bx1_s  = be2_s + 128;
    float* wx2_s  = bx1_s + 128;
    float* att_s  = wx2_s + 128;
    float* diff_s = att_s + 128;                // 384
    int* src_s = (int*)(diff_s + 384);
    int* dst_s = src_s + 128;

    int tid = threadIdx.x;
    int lane = tid & 31, w = tid >> 5;
    int g4 = lane >> 2, t4 = lane & 3;
    int m0 = (w & 3) * 32, n0 = (w >> 2) * 64;
    int e0 = blockIdx.x * 128;

    if (tid < 128) {
        int e = e0 + tid;
        int s = eidx[e], d = eidx[EE + e];
        src_s[tid] = s; dst_s[tid] = d;
        float dx = x[s * 3 + 0] - x[d * 3 + 0];
        float dy = x[s * 3 + 1] - x[d * 3 + 1];
        float dz = x[s * 3 + 2] - x[d * 3 + 2];
        diff_s[tid * 3 + 0] = dx; diff_s[tid * 3 + 1] = dy; diff_s[tid * 3 + 2] = dz;
        float dsq = dx * dx + dy * dy + dz * dz;
        watt_s[tid] = Watt[tid];
        be2_s[tid]  = be2[tid];
        bx1_s[tid]  = bx1[tid];
        wx2_s[tid]  = Wx2[tid];
        // build Es row: [dsq, ea0..7, 0 x7] fp16
        float4 a0 = *(const float4*)(ea + (size_t)e * 8);
        float4 a1 = *(const float4*)(ea + (size_t)e * 8 + 4);
        uint4 u0, u1;
        u0.x = packh2(dsq,  a0.x); u0.y = packh2(a0.y, a0.z);
        u0.z = packh2(a0.w, a1.x); u0.w = packh2(a1.y, a1.z);
        u1.x = packh2(a1.w, 0.f);  u1.y = 0u; u1.z = 0u; u1.w = 0u;
        *(uint4*)(Es + tid * ESTR) = u0;
        *(uint4*)(Es + tid * ESTR + 8) = u1;
    }
    {   // stage Wes from g_WeEh
        int n = tid >> 1, half = tid & 1;
        *(uint4*)(Wes + n * ESTR + half * 8) =
            *(const uint4*)((const uint16_t*)g_WeEh + n * 16 + half * 8);
    }
    stage_wt(g_We2h, 128, 0, WsB, tid);
    __syncthreads();

    {   // gather Ps_sum = Psrc[src] + Pdst[dst] (fp16) -> HsB
        int e = tid >> 1, j0 = (tid & 1) * 64;
        int s = src_s[e], d = dst_s[e];
        const uint4* ps = (const uint4*)((const uint16_t*)g_Psrch + (size_t)s * 128 + j0);
        const uint4* pd = (const uint4*)((const uint16_t*)g_Pdsth + (size_t)d * 128 + j0);
        uint16_t* dp = HsB + (size_t)e * HSTR + j0;
#pragma unroll
        for (int q = 0; q < 8; q++) {
            uint4 a = ps[q], b = pd[q];
            uint4 r;
            *(__half2*)&r.x = __hadd2(*(__half2*)&a.x, *(__half2*)&b.x);
            *(__half2*)&r.y = __hadd2(*(__half2*)&a.y, *(__half2*)&b.y);
            *(__half2*)&r.z = __hadd2(*(__half2*)&a.z, *(__half2*)&b.z);
            *(__half2*)&r.w = __hadd2(*(__half2*)&a.w, *(__half2*)&b.w);
            *(uint4*)(dp + 8 * q) = r;
        }
    }
    __syncthreads();

    float acc[2][8][4];
#pragma unroll
    for (int mt = 0; mt < 2; mt++)
#pragma unroll
        for (int j = 0; j < 8; j++)
#pragma unroll
            for (int q = 0; q < 4; q++) acc[mt][j][q] = 0.f;
    // mma0: edge-feature contribution (K=16)
    mma_gemm16<ESTR,ESTR>(Es, Wes, 16, m0, n0, g4, t4, acc);

    // epilogue0: hidden = silu(acc + Ps_sum), in place in HsB
#pragma unroll
    for (int mt = 0; mt < 2; mt++) {
        int rA = m0 + 16 * mt + g4, rB = rA + 8;
#pragma unroll
        for (int j = 0; j < 8; j++) {
            int c = n0 + 8 * j + 2 * t4;
            uint32_t ua = *(uint32_t*)(HsB + (size_t)rA * HSTR + c);
            uint32_t ub = *(uint32_t*)(HsB + (size_t)rB * HSTR + c);
            float2 fa = __half22float2(*(__half2*)&ua);
            float2 fb = __half22float2(*(__half2*)&ub);
            *(uint32_t*)(HsB + (size_t)rA * HSTR + c) =
                packh2(silu_f(acc[mt][j][0] + fa.x), silu_f(acc[mt][j][1] + fa.y));
            *(uint32_t*)(HsB + (size_t)rB * HSTR + c) =
                packh2(silu_f(acc[mt][j][2] + fb.x), silu_f(acc[mt][j][3] + fb.y));
        }
    }
    __syncthreads();

    // GEMM1: m = hidden @ We2
#pragma unroll
    for (int mt = 0; mt < 2; mt++)
#pragma unroll
        for (int j = 0; j < 8; j++)
#pragma unroll
            for (int q = 0; q < 4; q++) acc[mt][j][q] = 0.f;
    mma_gemm16<HSTR,KSTR>(HsB, WsB, 128, m0, n0, g4, t4, acc);

    // epilogue1: bias + att partial dot
    float pA[2], pB[2];
#pragma unroll
    for (int mt = 0; mt < 2; mt++) {
        pA[mt] = 0.f; pB[mt] = 0.f;
#pragma unroll
        for (int j = 0; j < 8; j++) {
            int c = n0 + 8 * j + 2 * t4;
            float b0 = be2_s[c], b1 = be2_s[c + 1];
            float w0 = watt_s[c], w1 = watt_s[c + 1];
            acc[mt][j][0] += b0; acc[mt][j][1] += b1;
            acc[mt][j][2] += b0; acc[mt][j][3] += b1;
            pA[mt] = fmaf(acc[mt][j][0], w0, fmaf(acc[mt][j][1], w1, pA[mt]));
            pB[mt] = fmaf(acc[mt][j][2], w0, fmaf(acc[mt][j][3], w1, pB[mt]));
        }
        pA[mt] += __shfl_xor_sync(0xffffffffu, pA[mt], 1);
        pA[mt] += __shfl_xor_sync(0xffffffffu, pA[mt], 2);
        pB[mt] += __shfl_xor_sync(0xffffffffu, pB[mt], 1);
        pB[mt] += __shfl_xor_sync(0xffffffffu, pB[mt], 2);
        if (t4 == 0) {
            red_s[(m0 + 16 * mt + g4) * 2 + (w >> 2)] = pA[mt];
            red_s[(m0 + 16 * mt + g4 + 8) * 2 + (w >> 2)] = pB[mt];
        }
    }
    __syncthreads();
    if (tid < 128) {
        float s = red_s[tid * 2] + red_s[tid * 2 + 1] + batt[0];
        att_s[tid] = 1.f / (1.f + __expf(-s));
    }
    __syncthreads();

    // gate + store m (fp16) into HsB; stage Wx1
#pragma unroll
    for (int mt = 0; mt < 2; mt++) {
        int rA = m0 + 16 * mt + g4;
        float aA = att_s[rA], aB = att_s[rA + 8];
#pragma unroll
        for (int j = 0; j < 8; j++) {
            int c = n0 + 8 * j + 2 * t4;
            *(uint32_t*)(HsB + (size_t)rA * HSTR + c) =
                packh2(acc[mt][j][0] * aA, acc[mt][j][1] * aA);
            *(uint32_t*)(HsB + (size_t)(rA + 8) * HSTR + c) =
                packh2(acc[mt][j][2] * aB, acc[mt][j][3] * aB);
        }
    }
    stage_wt(g_Wx1h, 128, 0, WsB, tid);
    __syncthreads();

    // scatter msg_agg from HsB (fp16 m)
    {
        int r = tid >> 1, j0 = (tid & 1) * 64;
        int d = dst_s[r];
        const uint16_t* hp = HsB + (size_t)r * HSTR + j0;
        float* p = (float*)g_msg4 + (size_t)d * 128 + j0;
#pragma unroll
        for (int q = 0; q < 8; q++) {
            uint4 raw = *(const uint4*)(hp + 8 * q);
            float2 f0 = __half22float2(*(__half2*)&raw.x);
            float2 f1 = __half22float2(*(__half2*)&raw.y);
            float2 f2 = __half22float2(*(__half2*)&raw.z);
            float2 f3 = __half22float2(*(__half2*)&raw.w);
            red_add_v4(p + 8 * q,     f0.x, f0.y, f1.x, f1.y);
            red_add_v4(p + 8 * q + 4, f2.x, f2.y, f3.x, f3.y);
        }
    }

    // GEMM2: g = silu(m @ Wx1 + bx1); coordw partial = g @ Wx2
#pragma unroll
    for (int mt = 0; mt < 2; mt++)
#pragma unroll
        for (int j = 0; j < 8; j++)
#pragma unroll
            for (int q = 0; q < 4; q++) acc[mt][j][q] = 0.f;
    mma_gemm16<HSTR,KSTR>(HsB, WsB, 128, m0, n0, g4, t4, acc);

#pragma unroll
    for (int mt = 0; mt < 2; mt++) {
        pA[mt] = 0.f; pB[mt] = 0.f;
#pragma unroll
        for (int j = 0; j < 8; j++) {
            int c = n0 + 8 * j + 2 * t4;
            float b0 = bx1_s[c], b1 = bx1_s[c + 1];
            float w0 = wx2_s[c], w1 = wx2_s[c + 1];
            float g0 = silu_f(acc[mt][j][0] + b0);
            float g1 = silu_f(acc[mt][j][1] + b1);
            float g2 = silu_f(acc[mt][j][2] + b0);
            float g3 = silu_f(acc[mt][j][3] + b1);
            pA[mt] = fmaf(g0, w0, fmaf(g1, w1, pA[mt]));
            pB[mt] = fmaf(g2, w0, fmaf(g3, w1, pB[mt]));
        }
        pA[mt] += __shfl_xor_sync(0xffffffffu, pA[mt], 1);
        pA[mt] += __shfl_xor_sync(0xffffffffu, pA[mt], 2);
        pB[mt] += __shfl_xor_sync(0xffffffffu, pB[mt], 1);
        pB[mt] += __shfl_xor_sync(0xffffffffu, pB[mt], 2);
        if (t4 == 0) {
            red_s[(m0 + 16 * mt + g4) * 2 + (w >> 2)] = pA[mt];
            red_s[(m0 + 16 * mt + g4 + 8) * 2 + (w >> 2)] = pB[mt];
        }
    }
    __syncthreads();
    if (tid < 128) {
        float s = red_s[tid * 2] + red_s[tid * 2 + 1] + bx2[0];
        float cw = tanhf(s);
        int d = dst_s[tid];
        red_add_f(g_coord + (size_t)d * 3 + 0, diff_s[tid * 3 + 0] * cw);
        red_add_f(g_coord + (size_t)d * 3 + 1, diff_s[tid * 3 + 1] * cw);
        red_add_f(g_coord + (size_t)d * 3 + 2, diff_s[tid * 3 + 2] * cw);
        red_add_f(g_deg + d, 1.0f);
    }
}

// =====================================================================
// Kernel C: node update (fp16 mma)
// =====================================================================
__global__ __launch_bounds__(256, 2) void kC(const float* __restrict__ h,
                                             const float* __restrict__ bh1,
                                             const float* __restrict__ bh2,
                                             float* __restrict__ out) {
    extern __shared__ float sm[];
    uint16_t* HsB = (uint16_t*)sm;
    uint16_t* WsB = HsB + 128 * HSTR;
    int tid = threadIdx.x;
    int lane = tid & 31, w = tid >> 5;
    int g4 = lane >> 2, t4 = lane & 3;
    int m0 = (w & 3) * 32, n0 = (w >> 2) * 64;
    int tile0 = blockIdx.x * 128;

    float acc[2][8][4];
#pragma unroll
    for (int mt = 0; mt < 2; mt++)
#pragma unroll
        for (int j = 0; j < 8; j++)
#pragma unroll
            for (int q = 0; q < 4; q++) acc[mt][j][q] = 0.f;

    for (int pass = 0; pass < 2; pass++) {
        const float* src = pass ? (const float*)g_msg4 : h;
        if (pass) __syncthreads();
        {   // stage A tile fp16
            int n = tid >> 1, kh = (tid & 1) * 64;
            int gn = tile0 + n;
            uint16_t* d = HsB + (size_t)n * HSTR + kh;
#pragma unroll
            for (int q = 0; q < 8; q++) {
                float4 v0 = make_float4(0.f, 0.f, 0.f, 0.f);
                float4 v1 = make_float4(0.f, 0.f, 0.f, 0.f);
                if (gn < NN) {
                    v0 = *(const float4*)(src + (size_t)gn * 128 + kh + q * 8);
                    v1 = *(const float4*)(src + (size_t)gn * 128 + kh + q * 8 + 4);
                }
                uint4 u;
                u.x = packh2(v0.x, v0.y); u.y = packh2(v0.z, v0.w);
                u.z = packh2(v1.x, v1.y); u.w = packh2(v1.z, v1.w);
                *(uint4*)(d + 8 * q) = u;
            }
        }
        stage_wt(g_Wh1h, 256, pass * 128, WsB, tid);
        __syncthreads();
        mma_gemm16<HSTR,KSTR>(HsB, WsB, 128, m0, n0, g4, t4, acc);
    }

    // g = silu(acc + bh1) -> HsB fp16
    __syncthreads();
#pragma unroll
    for (int mt = 0; mt < 2; mt++) {
        int rA = m0 + 16 * mt + g4;
#pragma unroll
        for (int j = 0; j < 8; j++) {
            int c = n0 + 8 * j + 2 * t4;
            float2 bb = *(const float2*)(bh1 + c);
            *(uint32_t*)(HsB + (size_t)rA * HSTR + c) =
                packh2(silu_f(acc[mt][j][0] + bb.x), silu_f(acc[mt][j][1] + bb.y));
            *(uint32_t*)(HsB + (size_t)(rA + 8) * HSTR + c) =
                packh2(silu_f(acc[mt][j][2] + bb.x), silu_f(acc[mt][j][3] + bb.y));
        }
    }
    stage_wt(g_Wh2h, 128, 0, WsB, tid);
    __syncthreads();

#pragma unroll
    for (int mt = 0; mt < 2; mt++)
#pragma unroll
        for (int j = 0; j < 8; j++)
#pragma unroll
            for (int q = 0; q < 4; q++) acc[mt][j][q] = 0.f;
    mma_gemm16<HSTR,KSTR>(HsB, WsB, 128, m0, n0, g4, t4, acc);

    // out = h + acc + bh2
#pragma unroll
    for (int mt = 0; mt < 2; mt++) {
        int rA = m0 + 16 * mt + g4;
        int gnA = tile0 + rA, gnB = gnA + 8;
#pragma unroll
        for (int j = 0; j < 8; j++) {
            int c = n0 + 8 * j + 2 * t4;
            float2 bb = *(const float2*)(bh2 + c);
            if (gnA < NN) {
                float2 hv = *(const float2*)(h + (size_t)gnA * 128 + c);
                *(float2*)(out + (size_t)gnA * 128 + c) =
                    make_float2(hv.x + acc[mt][j][0] + bb.x,
                                hv.y + acc[mt][j][1] + bb.y);
            }
            if (gnB < NN) {
                float2 hv = *(const float2*)(h + (size_t)gnB * 128 + c);
                *(float2*)(out + (size_t)gnB * 128 + c) =
                    make_float2(hv.x + acc[mt][j][2] + bb.x,
                                hv.y + acc[mt][j][3] + bb.y);
            }
        }
    }
}

// ---- x_out ----
__global__ void kX(const float* __restrict__ x, float* __restrict__ out) {
    int n = blockIdx.x * blockDim.x + threadIdx.x;
    if (n < NN) {
        float inv = 1.f / (g_deg[n] + 1.f);
        float* o = out + (size_t)NN * 128 + (size_t)n * 3;
        o[0] = x[n * 3 + 0] + g_coord[n * 3 + 0] * inv;
        o[1] = x[n * 3 + 1] + g_coord[n * 3 + 1] * inv;
        o[2] = x[n * 3 + 2] + g_coord[n * 3 + 2] * inv;
    }
}

extern "C" void kernel_launch(void* const* d_in, const int* in_sizes, int n_in,
                              void* d_out, int out_size) {
    const float* h    = (const float*)d_in[0];
    const float* x    = (const float*)d_in[1];
    const float* ea   = (const float*)d_in[2];
    const float* temb = (const float*)d_in[3];
    const float* We1w = (const float*)d_in[4];
    const float* We1b = (const float*)d_in[5];
    const float* We2w = (const float*)d_in[6];
    const float* We2b = (const float*)d_in[7];
    const float* Wattw = (const float*)d_in[8];
    const float* Wattb = (const float*)d_in[9];
    const float* Wx1w = (const float*)d_in[10];
    const float* Wx1b = (const float*)d_in[11];
    const float* Wx2w = (const float*)d_in[12];
    const float* Wx2b = (const float*)d_in[13];
    const float* Wh1w = (const float*)d_in[14];
    const float* Wh1b = (const float*)d_in[15];
    const float* Wh2w = (const float*)d_in[16];
    const float* Wh2b = (const float*)d_in[17];
    const int*   eidx = (const int*)d_in[18];
    float* out = (float*)d_out;

    const int smA = 128 * (HSTR + KSTR + TSTR) * 2;
    const int smB = 128 * (HSTR + KSTR) * 2 + 128 * ESTR * 2 * 2 +
                    (256 + 128 * 5 + 384) * 4 + 256 * 4 + 512;
    const int smC = 128 * (HSTR + KSTR) * 2;
    cudaFuncSetAttribute(kA, cudaFuncAttributeMaxDynamicSharedMemorySize, smA);
    cudaFuncSetAttribute(kB, cudaFuncAttributeMaxDynamicSharedMemorySize, smB);
    cudaFuncSetAttribute(kC, cudaFuncAttributeMaxDynamicSharedMemorySize, smC);

    kZero<<<2048, 256>>>();
    kW<<<360, 256>>>(We1w, We2w, Wx1w, Wh1w, Wh2w);
    kA<<<(NN + 127) / 128, 256, smA>>>(h, temb, We1b);
    kB<<<EE / 128, 256, smB>>>(x, ea, eidx, We2b,
                               Wattw, Wattb, Wx1b, Wx2w, Wx2b);
    kC<<<(NN + 127) / 128, 256, smC>>>(h, Wh1b, Wh2b, out);
    kX<<<(NN + 255) / 256, 256>>>(x, out);
}